// round 5
// baseline (speedup 1.0000x reference)
#include <cuda_runtime.h>
#include <cstdint>

typedef unsigned long long u64;

#define B_      32
#define QL      4
#define DIM     2048
#define HEADS   16
#define HD      128
#define KVL     8192
#define M_      (B_*QL)          /* 128 rows for projection GEMMs        */
#define NQKV    2304             /* 2048 q-cols + 128 k + 128 v          */
#define NSPLIT  8
#define CHUNK   (KVL/NSPLIT)     /* 1024 keys per attention block        */
#define SCALE   0.08838834764831845f

/* ------------------------------------------------------------------ */
/* scratch (device globals — no allocations allowed)                   */
/* ------------------------------------------------------------------ */
__device__ float g_part[NSPLIT * M_ * NQKV];            /* split-K partials (both GEMMs) */
__device__ float g_qkv [M_ * NQKV];                     /* q | k_new | v_new             */
__device__ float g_po  [(size_t)B_ * 64 * NSPLIT * HD]; /* partial O per KV split        */
__device__ float g_pml [B_ * 64 * NSPLIT * 2];          /* partial (m, l)                */
__device__ float g_o   [M_ * DIM];                      /* combined attention output     */

/* ------------------------------------------------------------------ */
/* packed f32x2 helpers (Blackwell-only FFMA2 path)                    */
/* ------------------------------------------------------------------ */
__device__ __forceinline__ u64 pack2(float x) {
    u64 r; asm("mov.b64 %0, {%1, %1};" : "=l"(r) : "f"(x)); return r;
}
__device__ __forceinline__ void fma2(u64& d, u64 a, u64 b) {
    asm("fma.rn.f32x2 %0, %1, %2, %0;" : "+l"(d) : "l"(a), "l"(b));
}
__device__ __forceinline__ void mul2(u64& d, u64 a) {
    asm("mul.rn.f32x2 %0, %0, %1;" : "+l"(d) : "l"(a));
}
__device__ __forceinline__ float2 unpk(u64 v) {
    float2 f; asm("mov.b64 {%0, %1}, %2;" : "=f"(f.x), "=f"(f.y) : "l"(v)); return f;
}

/* ------------------------------------------------------------------ */
/* Kernel: split-K GEMM, 64x64 tile, K-chunk 256 per blockIdx.z        */
/* C_part[z][m][ncol0+n] = sum_{k in chunk z} A[m][k] * B[k][n]        */
/* ------------------------------------------------------------------ */
__global__ __launch_bounds__(256) void gemm64(
    const float* __restrict__ A, int lda,
    const float* __restrict__ B, int ldb,
    int ncol0)
{
    __shared__ u64   sA2[16][65];   /* A tile, transposed, pre-duplicated pairs */
    __shared__ float sB[16][64];

    const int tid = threadIdx.x;
    const int tx  = tid & 15, ty = tid >> 4;
    const int m0  = blockIdx.y * 64, n0 = blockIdx.x * 64;
    const int k0  = blockIdx.z * 256;

    u64 acc[4][2];
#pragma unroll
    for (int i = 0; i < 4; i++) { acc[i][0] = 0ull; acc[i][1] = 0ull; }

    const int ar = tid >> 2, akq = tid & 3;     /* A-load map: 64 rows x 4 float4 */
    const int bk = tid >> 4, bc  = tid & 15;    /* B-load map: 16 rows x 16 float4 */

    for (int kt = 0; kt < 256; kt += 16) {
        float4 av = *(const float4*)&A[(size_t)(m0 + ar) * lda + k0 + kt + akq * 4];
        float4 bv = *(const float4*)&B[(size_t)(k0 + kt + bk) * ldb + n0 + bc * 4];
        __syncthreads();
        sA2[akq * 4 + 0][ar] = pack2(av.x);
        sA2[akq * 4 + 1][ar] = pack2(av.y);
        sA2[akq * 4 + 2][ar] = pack2(av.z);
        sA2[akq * 4 + 3][ar] = pack2(av.w);
        *(float4*)&sB[bk][bc * 4] = bv;
        __syncthreads();
#pragma unroll
        for (int kk = 0; kk < 16; kk++) {
            ulonglong2 b2 = *(const ulonglong2*)&sB[kk][tx * 4];
#pragma unroll
            for (int i = 0; i < 4; i++) {
                u64 a2 = sA2[kk][ty * 4 + i];
                fma2(acc[i][0], a2, b2.x);
                fma2(acc[i][1], a2, b2.y);
            }
        }
    }

    float* dst = g_part + (size_t)(blockIdx.z * M_ + m0) * NQKV + ncol0 + n0;
#pragma unroll
    for (int i = 0; i < 4; i++) {
        float2 f0 = unpk(acc[i][0]), f1 = unpk(acc[i][1]);
        float4 o4 = make_float4(f0.x, f0.y, f1.x, f1.y);
        *(float4*)&dst[(size_t)(ty * 4 + i) * NQKV + tx * 4] = o4;
    }
}

/* ------------------------------------------------------------------ */
/* Reduce split-K partials for QKV projection, add biases             */
/* ------------------------------------------------------------------ */
__global__ void reduce_qkv(const float* __restrict__ bq,
                           const float* __restrict__ bk,
                           const float* __restrict__ bv)
{
    int idx = blockIdx.x * 256 + threadIdx.x;        /* over float4s: 128*2304/4 = 73728 */
    if (idx >= M_ * NQKV / 4) return;
    int m = idx / (NQKV / 4);
    int n = (idx % (NQKV / 4)) * 4;
    float4 s = make_float4(0.f, 0.f, 0.f, 0.f);
#pragma unroll
    for (int sk = 0; sk < NSPLIT; sk++) {
        float4 v = *(const float4*)&g_part[(size_t)(sk * M_ + m) * NQKV + n];
        s.x += v.x; s.y += v.y; s.z += v.z; s.w += v.w;
    }
    float4 bb;
    if (n < 2048)       bb = *(const float4*)&bq[n];
    else if (n < 2176)  bb = *(const float4*)&bk[n - 2048];
    else                bb = *(const float4*)&bv[n - 2176];
    s.x += bb.x; s.y += bb.y; s.z += bb.z; s.w += bb.w;
    *(float4*)&g_qkv[(size_t)m * NQKV + n] = s;
}

/* ------------------------------------------------------------------ */
/* Fused flash attention over one 1024-key chunk of one batch          */
/* grid = (NSPLIT, B); 256 threads; dynamic smem ~84KB                 */
/* ------------------------------------------------------------------ */
__global__ __launch_bounds__(256) void attn_kernel(
    const float* __restrict__ bias,
    const float* __restrict__ cache_k,
    const float* __restrict__ cache_v)
{
    extern __shared__ float sm[];
    float* sQ = sm;                      /* 64 x 128           */
    float* sK = sm + 64 * 128;           /* 32 x 132 (padded)  */
    float* sV = sK + 32 * 132;           /* 32 x 132           */
    float* sS = sV + 32 * 132;           /* 64 x 36  (padded)  */
    float* sB = sS + 64 * 36;            /* 64 x 36            */
    float* sM = sB + 64 * 36;
    float* sL = sM + 64;
    float* sA = sL + 64;

    const int tid = threadIdx.x;
    const int s   = blockIdx.x;
    const int b   = blockIdx.y;

    /* row/col maps shared by S-phase and O-phase */
    const int stx = tid & 15;
    const int r0  = (tid >> 4) * 4;      /* 4 rows per thread          */
    const int oc0 = stx * 8;             /* 8 O columns per thread     */

    /* load Q tile: rows r = h*4+q */
    for (int idx = tid; idx < 64 * 32; idx += 256) {
        int r = idx >> 5, c4 = (idx & 31) << 2;
        int q = r & 3, h = r >> 2;
        *(float4*)&sQ[r * 128 + c4] =
            *(const float4*)&g_qkv[(size_t)(b * QL + q) * NQKV + h * HD + c4];
    }
    if (tid < 64) { sM[tid] = -1e30f; sL[tid] = 0.f; }

    u64 oacc[4][4];
#pragma unroll
    for (int i = 0; i < 4; i++)
#pragma unroll
        for (int c = 0; c < 4; c++) oacc[i][c] = 0ull;

    for (int t = 0; t < CHUNK / 32; t++) {
        const int kb = s * CHUNK + t * 32;
        __syncthreads();                 /* guards prior O-phase / Q-load */

        /* ---- load K,V subtile (rolling-cache patched) + bias tile ---- */
        for (int idx = tid; idx < 32 * 32; idx += 256) {
            int jr = idx >> 5, c4 = (idx & 31) << 2;
            int jg = kb + jr;
            const float *srck, *srcv;
            if (jg < KVL - QL) {
                size_t off = ((size_t)b * KVL + jg + QL) * HD + c4;
                srck = cache_k + off; srcv = cache_v + off;
            } else {
                size_t mrow = (size_t)(b * QL + (jg - (KVL - QL))) * NQKV;
                srck = g_qkv + mrow + 2048 + c4;
                srcv = g_qkv + mrow + 2176 + c4;
            }
            *(float4*)&sK[jr * 132 + c4] = *(const float4*)srck;
            *(float4*)&sV[jr * 132 + c4] = *(const float4*)srcv;
        }
        for (int idx = tid; idx < 64 * 8; idx += 256) {
            int rr = idx >> 3, c4 = (idx & 7) << 2;
            *(float4*)&sB[rr * 36 + c4] =
                *(const float4*)&bias[((size_t)b * 64 + rr) * KVL + kb + c4];
        }
        __syncthreads();

        /* ---- S = Q K^T (f32x2 over e) ---- */
        {
            u64 accA[4], accB[4];
#pragma unroll
            for (int i = 0; i < 4; i++) { accA[i] = 0ull; accB[i] = 0ull; }
            const float* kp0 = &sK[stx * 132];
            const float* kp1 = &sK[(stx + 16) * 132];
#pragma unroll 4
            for (int e = 0; e < 128; e += 4) {
                ulonglong2 kA = *(const ulonglong2*)&kp0[e];
                ulonglong2 kB = *(const ulonglong2*)&kp1[e];
#pragma unroll
                for (int i = 0; i < 4; i++) {
                    ulonglong2 qv = *(const ulonglong2*)&sQ[(r0 + i) * 128 + e];
                    fma2(accA[i], qv.x, kA.x); fma2(accA[i], qv.y, kA.y);
                    fma2(accB[i], qv.x, kB.x); fma2(accB[i], qv.y, kB.y);
                }
            }
#pragma unroll
            for (int i = 0; i < 4; i++) {
                float2 a = unpk(accA[i]);
                float2 c = unpk(accB[i]);
                sS[(r0 + i) * 36 + stx]      = (a.x + a.y) * SCALE;
                sS[(r0 + i) * 36 + stx + 16] = (c.x + c.y) * SCALE;
            }
        }
        __syncthreads();

        /* ---- online softmax per row (64 threads) ---- */
        if (tid < 64) {
            float* srow = &sS[tid * 36];
            float* brow = &sB[tid * 36];
            float mx = -1e30f;
#pragma unroll
            for (int j = 0; j < 32; j++) {
                float v = srow[j] + brow[j];
                srow[j] = v;
                mx = fmaxf(mx, v);
            }
            float mo = sM[tid];
            float mn = fmaxf(mo, mx);
            float al = __expf(mo - mn);
            float ls = 0.f;
#pragma unroll
            for (int j = 0; j < 32; j++) {
                float p = __expf(srow[j] - mn);
                srow[j] = p;
                ls += p;
            }
            sM[tid] = mn;
            sL[tid] = sL[tid] * al + ls;
            sA[tid] = al;
        }
        __syncthreads();

        /* ---- O = alpha*O + P V (f32x2 over columns) ---- */
        {
#pragma unroll
            for (int i = 0; i < 4; i++) {
                u64 a2 = pack2(sA[r0 + i]);
#pragma unroll
                for (int c = 0; c < 4; c++) mul2(oacc[i][c], a2);
            }
            for (int j = 0; j < 32; j++) {
                const float* vp = &sV[j * 132 + oc0];
                ulonglong2 v0 = *(const ulonglong2*)&vp[0];
                ulonglong2 v1 = *(const ulonglong2*)&vp[4];
#pragma unroll
                for (int i = 0; i < 4; i++) {
                    u64 p2 = pack2(sS[(r0 + i) * 36 + j]);
                    fma2(oacc[i][0], p2, v0.x);
                    fma2(oacc[i][1], p2, v0.y);
                    fma2(oacc[i][2], p2, v1.x);
                    fma2(oacc[i][3], p2, v1.y);
                }
            }
        }
    }

    /* ---- epilogue: partial O and (m,l) ---- */
#pragma unroll
    for (int i = 0; i < 4; i++) {
        int r = r0 + i;
        size_t base = (((size_t)b * 64 + r) * NSPLIT + s) * HD + oc0;
        float2 f0 = unpk(oacc[i][0]), f1 = unpk(oacc[i][1]);
        float2 f2 = unpk(oacc[i][2]), f3 = unpk(oacc[i][3]);
        *(float4*)&g_po[base]     = make_float4(f0.x, f0.y, f1.x, f1.y);
        *(float4*)&g_po[base + 4] = make_float4(f2.x, f2.y, f3.x, f3.y);
    }
    if (tid < 64) {
        size_t pb = (((size_t)b * 64 + tid) * NSPLIT + s) * 2;
        g_pml[pb]     = sM[tid];
        g_pml[pb + 1] = sL[tid];
    }
}

/* ------------------------------------------------------------------ */
/* Combine the NSPLIT partial softmax results                          */
/* ------------------------------------------------------------------ */
__global__ void combine_kernel()
{
    int b = blockIdx.x, tid = threadIdx.x;
    int r = tid >> 2, e0 = (tid & 3) * 32;
    size_t pbase = ((size_t)b * 64 + r) * NSPLIT;

    float ms[NSPLIT], ls[NSPLIT], w[NSPLIT];
    float M = -1e30f;
#pragma unroll
    for (int s = 0; s < NSPLIT; s++) {
        ms[s] = g_pml[(pbase + s) * 2];
        ls[s] = g_pml[(pbase + s) * 2 + 1];
        M = fmaxf(M, ms[s]);
    }
    float L = 0.f;
#pragma unroll
    for (int s = 0; s < NSPLIT; s++) { w[s] = __expf(ms[s] - M); L += ls[s] * w[s]; }
    float inv = 1.f / L;
#pragma unroll
    for (int s = 0; s < NSPLIT; s++) w[s] *= inv;

    int q = r & 3, h = r >> 2;
    float* dst = g_o + (size_t)(b * QL + q) * DIM + h * HD;
    for (int e = e0; e < e0 + 32; e += 4) {
        float4 acc = make_float4(0.f, 0.f, 0.f, 0.f);
#pragma unroll
        for (int s = 0; s < NSPLIT; s++) {
            float4 v = *(const float4*)&g_po[(pbase + s) * HD + e];
            acc.x += v.x * w[s]; acc.y += v.y * w[s];
            acc.z += v.z * w[s]; acc.w += v.w * w[s];
        }
        *(float4*)&dst[e] = acc;
    }
}

/* ------------------------------------------------------------------ */
/* Reduce split-K partials for output projection + bo -> d_out         */
/* ------------------------------------------------------------------ */
__global__ void reduce_out(const float* __restrict__ bo, float* __restrict__ out)
{
    int idx = blockIdx.x * 256 + threadIdx.x;        /* 128*2048/4 = 65536 float4s */
    int m = idx >> 9;
    int n = (idx & 511) << 2;
    float4 s = *(const float4*)&bo[n];
#pragma unroll
    for (int sk = 0; sk < NSPLIT; sk++) {
        float4 v = *(const float4*)&g_part[(size_t)(sk * M_ + m) * NQKV + n];
        s.x += v.x; s.y += v.y; s.z += v.z; s.w += v.w;
    }
    *(float4*)&out[(size_t)m * DIM + n] = s;
}

/* ------------------------------------------------------------------ */
extern "C" void kernel_launch(void* const* d_in, const int* in_sizes, int n_in,
                              void* d_out, int out_size)
{
    const float* x         = (const float*)d_in[0];
    const float* attn_bias = (const float*)d_in[1];
    const float* cache_k   = (const float*)d_in[2];
    const float* cache_v   = (const float*)d_in[3];
    const float* wq        = (const float*)d_in[4];
    const float* bq        = (const float*)d_in[5];
    const float* wk        = (const float*)d_in[6];
    const float* bk        = (const float*)d_in[7];
    const float* wv        = (const float*)d_in[8];
    const float* bv        = (const float*)d_in[9];
    const float* wo        = (const float*)d_in[10];
    const float* bo        = (const float*)d_in[11];
    float*       out       = (float*)d_out;

    static bool attr_set = false;
    (void)attr_set;
    cudaFuncSetAttribute(attn_kernel,
                         cudaFuncAttributeMaxDynamicSharedMemorySize, 86000);

    float* go_ptr = nullptr;
    cudaGetSymbolAddress((void**)&go_ptr, g_o);

    /* 1) QKV projections (split-K) */
    gemm64<<<dim3(32, 2, NSPLIT), 256>>>(x, DIM, wq, 2048, 0);
    gemm64<<<dim3(2, 2, NSPLIT), 256>>>(x, DIM, wk, 128, 2048);
    gemm64<<<dim3(2, 2, NSPLIT), 256>>>(x, DIM, wv, 128, 2176);
    reduce_qkv<<<288, 256>>>(bq, bk, bv);

    /* 2) fused flash attention, split over KV */
    attn_kernel<<<dim3(NSPLIT, B_), 256, 86000>>>(attn_bias, cache_k, cache_v);

    /* 3) combine split-softmax partials */
    combine_kernel<<<B_, 256>>>();

    /* 4) output projection (split-K) */
    gemm64<<<dim3(32, 2, NSPLIT), 256>>>(go_ptr, DIM, wo, DIM, 0);
    reduce_out<<<256, 256>>>(bo, out);
}

// round 7
// speedup vs baseline: 1.0693x; 1.0693x over previous
#include <cuda_runtime.h>
#include <cstdint>

typedef unsigned long long u64;

#define B_      32
#define QL      4
#define DIM     2048
#define HEADS   16
#define HD      128
#define KVL     8192
#define M_      (B_*QL)          /* 128 rows for projection GEMMs        */
#define NQKV    2304             /* 2048 q-cols + 128 k + 128 v          */
#define NSPLIT  8
#define CHUNK   (KVL/NSPLIT)     /* 1024 keys per attention block        */
#define NT      (CHUNK/32)       /* 32-key subtiles per block            */
#define SCALE   0.08838834764831845f

/* ------------------------------------------------------------------ */
/* scratch (device globals — no allocations allowed)                   */
/* ------------------------------------------------------------------ */
__device__ float g_part[NSPLIT * M_ * NQKV];            /* split-K partials (both GEMMs) */
__device__ float g_qkv [M_ * NQKV];                     /* q | k_new | v_new             */
__device__ float g_po  [(size_t)B_ * 64 * NSPLIT * HD]; /* partial O per KV split        */
__device__ float g_pml [B_ * 64 * NSPLIT * 2];          /* partial (m, l)                */
__device__ float g_o   [M_ * DIM];                      /* combined attention output     */

/* ------------------------------------------------------------------ */
/* packed f32x2 helpers (Blackwell-only FFMA2 path)                    */
/* ------------------------------------------------------------------ */
__device__ __forceinline__ u64 pack2(float x) {
    u64 r; asm("mov.b64 %0, {%1, %1};" : "=l"(r) : "f"(x)); return r;
}
__device__ __forceinline__ void fma2(u64& d, u64 a, u64 b) {
    asm("fma.rn.f32x2 %0, %1, %2, %0;" : "+l"(d) : "l"(a), "l"(b));
}
__device__ __forceinline__ void mul2(u64& d, u64 a) {
    asm("mul.rn.f32x2 %0, %0, %1;" : "+l"(d) : "l"(a));
}
__device__ __forceinline__ float2 unpk(u64 v) {
    float2 f; asm("mov.b64 {%0, %1}, %2;" : "=f"(f.x), "=f"(f.y) : "l"(v)); return f;
}
__device__ __forceinline__ void cp16(uint32_t saddr, const void* g) {
    asm volatile("cp.async.cg.shared.global [%0], [%1], 16;" :: "r"(saddr), "l"(g));
}
#define CP_COMMIT() asm volatile("cp.async.commit_group;")
#define CP_WAIT0()  asm volatile("cp.async.wait_group 0;")

/* ------------------------------------------------------------------ */
/* Kernel: split-K GEMM, 64x64 tile, K-chunk 256 per blockIdx.z        */
/* ------------------------------------------------------------------ */
__global__ __launch_bounds__(256) void gemm64(
    const float* __restrict__ A, int lda,
    const float* __restrict__ B, int ldb,
    int ncol0)
{
    __shared__ u64   sA2[16][65];
    __shared__ float sB[16][64];

    const int tid = threadIdx.x;
    const int tx  = tid & 15, ty = tid >> 4;
    const int m0  = blockIdx.y * 64, n0 = blockIdx.x * 64;
    const int k0  = blockIdx.z * 256;

    u64 acc[4][2];
#pragma unroll
    for (int i = 0; i < 4; i++) { acc[i][0] = 0ull; acc[i][1] = 0ull; }

    const int ar = tid >> 2, akq = tid & 3;
    const int bk = tid >> 4, bc  = tid & 15;

    for (int kt = 0; kt < 256; kt += 16) {
        float4 av = *(const float4*)&A[(size_t)(m0 + ar) * lda + k0 + kt + akq * 4];
        float4 bv = *(const float4*)&B[(size_t)(k0 + kt + bk) * ldb + n0 + bc * 4];
        __syncthreads();
        sA2[akq * 4 + 0][ar] = pack2(av.x);
        sA2[akq * 4 + 1][ar] = pack2(av.y);
        sA2[akq * 4 + 2][ar] = pack2(av.z);
        sA2[akq * 4 + 3][ar] = pack2(av.w);
        *(float4*)&sB[bk][bc * 4] = bv;
        __syncthreads();
#pragma unroll
        for (int kk = 0; kk < 16; kk++) {
            ulonglong2 b2 = *(const ulonglong2*)&sB[kk][tx * 4];
#pragma unroll
            for (int i = 0; i < 4; i++) {
                u64 a2 = sA2[kk][ty * 4 + i];
                fma2(acc[i][0], a2, b2.x);
                fma2(acc[i][1], a2, b2.y);
            }
        }
    }

    float* dst = g_part + (size_t)(blockIdx.z * M_ + m0) * NQKV + ncol0 + n0;
#pragma unroll
    for (int i = 0; i < 4; i++) {
        float2 f0 = unpk(acc[i][0]), f1 = unpk(acc[i][1]);
        float4 o4 = make_float4(f0.x, f0.y, f1.x, f1.y);
        *(float4*)&dst[(size_t)(ty * 4 + i) * NQKV + tx * 4] = o4;
    }
}

/* ------------------------------------------------------------------ */
/* Reduce split-K partials for QKV projection, add biases             */
/* ------------------------------------------------------------------ */
__global__ void reduce_qkv(const float* __restrict__ bq,
                           const float* __restrict__ bk,
                           const float* __restrict__ bv)
{
    int idx = blockIdx.x * 256 + threadIdx.x;
    if (idx >= M_ * NQKV / 4) return;
    int m = idx / (NQKV / 4);
    int n = (idx % (NQKV / 4)) * 4;
    float4 s = make_float4(0.f, 0.f, 0.f, 0.f);
#pragma unroll
    for (int sk = 0; sk < NSPLIT; sk++) {
        float4 v = *(const float4*)&g_part[(size_t)(sk * M_ + m) * NQKV + n];
        s.x += v.x; s.y += v.y; s.z += v.z; s.w += v.w;
    }
    float4 bb;
    if (n < 2048)       bb = *(const float4*)&bq[n];
    else if (n < 2176)  bb = *(const float4*)&bk[n - 2048];
    else                bb = *(const float4*)&bv[n - 2176];
    s.x += bb.x; s.y += bb.y; s.z += bb.z; s.w += bb.w;
    *(float4*)&g_qkv[(size_t)m * NQKV + n] = s;
}

/* ------------------------------------------------------------------ */
/* Fused flash attention, register softmax + cp.async double buffer    */
/* grid = (NSPLIT, B); 256 threads; dynamic smem ~99KB                 */
/*   smem: sQ 64x132 | sK[2] 32x132 | sV[2] 32x132                    */
/* ------------------------------------------------------------------ */
#define QSTR 132
#define KSTR 132
#define SQ_ELEMS (64 * QSTR)
#define KV_ELEMS (32 * KSTR)
#define ATTN_SMEM ((SQ_ELEMS + 4 * KV_ELEMS) * 4)

__global__ __launch_bounds__(256) void attn_kernel(
    const float* __restrict__ bias,
    const float* __restrict__ cache_k,
    const float* __restrict__ cache_v)
{
    extern __shared__ float sm[];
    float* sQ  = sm;
    float* sK0 = sm + SQ_ELEMS;
    float* sV0 = sK0 + 2 * KV_ELEMS;

    const int tid  = threadIdx.x;
    const int lane = tid & 31;
    const int s    = blockIdx.x;
    const int b    = blockIdx.y;

    const int stx = tid & 15;            /* S col / O col group        */
    const int r0  = (tid >> 4) * 4;      /* 4 rows per thread          */
    const int oc0 = stx * 8;             /* 8 O columns per thread     */

    const uint32_t skb = (uint32_t)__cvta_generic_to_shared(sK0);
    const uint32_t svb = (uint32_t)__cvta_generic_to_shared(sV0);

    /* load Q tile (rows r = h*4+q), padded stride */
    for (int idx = tid; idx < 64 * 32; idx += 256) {
        int r = idx >> 5, c4 = (idx & 31) << 2;
        int q = r & 3, h = r >> 2;
        *(float4*)&sQ[r * QSTR + c4] =
            *(const float4*)&g_qkv[(size_t)(b * QL + q) * NQKV + h * HD + c4];
    }

    /* per-thread cp.async source precompute helper (4 lines each for K,V) */
    const int jr_ = tid >> 3;            /* 0..31: K/V row handled (x8 threads/row) */
    const int c4_ = (tid & 7) << 4;      /* float offset, 4 threads... (8 x 16 floats=128) */
    /* each thread copies one 16B segment per line group; 1024 float4 / 256 thr = 4 each.
       map: idx = tid + k*256 -> jr = idx>>5, c4 = (idx&31)<<2  */
    (void)jr_; (void)c4_;

    const int kb0 = s * CHUNK;

    /* issue tile 0 */
    {
        int t = 0;
        float* dk = sK0 + (t & 1) * KV_ELEMS;
        float* dv = sV0 + (t & 1) * KV_ELEMS;
        (void)dk; (void)dv;
#pragma unroll
        for (int k = 0; k < 4; k++) {
            int idx = tid + k * 256;
            int jr = idx >> 5, c4 = (idx & 31) << 2;
            int jg = kb0 + jr;
            const float *srck, *srcv;
            if (jg < KVL - QL) {
                size_t off = ((size_t)b * KVL + jg + QL) * HD + c4;
                srck = cache_k + off; srcv = cache_v + off;
            } else {
                size_t mrow = (size_t)(b * QL + (jg - (KVL - QL))) * NQKV;
                srck = g_qkv + mrow + 2048 + c4;
                srcv = g_qkv + mrow + 2176 + c4;
            }
            uint32_t so = (uint32_t)((jr * KSTR + c4) * 4);
            cp16(skb + (t & 1) * (KV_ELEMS * 4) + so, srck);
            cp16(svb + (t & 1) * (KV_ELEMS * 4) + so, srcv);
        }
        CP_COMMIT();
    }

    float mreg[4], lreg[4];
#pragma unroll
    for (int i = 0; i < 4; i++) { mreg[i] = -1e30f; lreg[i] = 0.f; }

    u64 oacc[4][4];
#pragma unroll
    for (int i = 0; i < 4; i++)
#pragma unroll
        for (int c = 0; c < 4; c++) oacc[i][c] = 0ull;

    const float* bptr = bias + ((size_t)b * 64 + r0) * KVL + kb0 + stx;

    for (int t = 0; t < NT; t++) {
        CP_WAIT0();
        __syncthreads();                 /* buffer t visible; prev compute done */

        /* prefetch tile t+1 into the other buffer */
        if (t + 1 < NT) {
            int tn = t + 1;
#pragma unroll
            for (int k = 0; k < 4; k++) {
                int idx = tid + k * 256;
                int jr = idx >> 5, c4 = (idx & 31) << 2;
                int jg = kb0 + tn * 32 + jr;
                const float *srck, *srcv;
                if (jg < KVL - QL) {
                    size_t off = ((size_t)b * KVL + jg + QL) * HD + c4;
                    srck = cache_k + off; srcv = cache_v + off;
                } else {
                    size_t mrow = (size_t)(b * QL + (jg - (KVL - QL))) * NQKV;
                    srck = g_qkv + mrow + 2048 + c4;
                    srcv = g_qkv + mrow + 2176 + c4;
                }
                uint32_t so = (uint32_t)((jr * KSTR + c4) * 4);
                cp16(skb + (tn & 1) * (KV_ELEMS * 4) + so, srck);
                cp16(svb + (tn & 1) * (KV_ELEMS * 4) + so, srcv);
            }
            CP_COMMIT();
        }

        /* bias for this tile straight from gmem (single touch) */
        float bA[4], bB[4];
#pragma unroll
        for (int i = 0; i < 4; i++) {
            bA[i] = bptr[(size_t)i * KVL + t * 32];
            bB[i] = bptr[(size_t)i * KVL + t * 32 + 16];
        }

        const float* sKb = sK0 + (t & 1) * KV_ELEMS;
        const float* sVb = sV0 + (t & 1) * KV_ELEMS;

        /* ---- S = Q K^T (f32x2 over e), kept in registers ---- */
        u64 accA[4], accB[4];
#pragma unroll
        for (int i = 0; i < 4; i++) { accA[i] = 0ull; accB[i] = 0ull; }
        {
            const float* kp0 = &sKb[stx * KSTR];
            const float* kp1 = &sKb[(stx + 16) * KSTR];
#pragma unroll 4
            for (int e = 0; e < 128; e += 4) {
                ulonglong2 kA = *(const ulonglong2*)&kp0[e];
                ulonglong2 kB = *(const ulonglong2*)&kp1[e];
#pragma unroll
                for (int i = 0; i < 4; i++) {
                    ulonglong2 qv = *(const ulonglong2*)&sQ[(r0 + i) * QSTR + e];
                    fma2(accA[i], qv.x, kA.x); fma2(accA[i], qv.y, kA.y);
                    fma2(accB[i], qv.x, kB.x); fma2(accB[i], qv.y, kB.y);
                }
            }
        }

        /* ---- online softmax: half-warp shfl reductions, all warps ---- */
        float pA[4], pB[4];
#pragma unroll
        for (int i = 0; i < 4; i++) {
            float2 a = unpk(accA[i]);
            float2 c = unpk(accB[i]);
            float vA = (a.x + a.y) * SCALE + bA[i];
            float vB = (c.x + c.y) * SCALE + bB[i];
            float mx = fmaxf(vA, vB);
            mx = fmaxf(mx, __shfl_xor_sync(0xffffffffu, mx, 8, 16));
            mx = fmaxf(mx, __shfl_xor_sync(0xffffffffu, mx, 4, 16));
            mx = fmaxf(mx, __shfl_xor_sync(0xffffffffu, mx, 2, 16));
            mx = fmaxf(mx, __shfl_xor_sync(0xffffffffu, mx, 1, 16));
            float mn = fmaxf(mreg[i], mx);
            float al = __expf(mreg[i] - mn);
            pA[i] = __expf(vA - mn);
            pB[i] = __expf(vB - mn);
            float ls = pA[i] + pB[i];
            ls += __shfl_xor_sync(0xffffffffu, ls, 8, 16);
            ls += __shfl_xor_sync(0xffffffffu, ls, 4, 16);
            ls += __shfl_xor_sync(0xffffffffu, ls, 2, 16);
            ls += __shfl_xor_sync(0xffffffffu, ls, 1, 16);
            lreg[i] = lreg[i] * al + ls;
            mreg[i] = mn;
            u64 a2 = pack2(al);
            mul2(oacc[i][0], a2); mul2(oacc[i][1], a2);
            mul2(oacc[i][2], a2); mul2(oacc[i][3], a2);
        }

        /* ---- O += P V : P broadcast via shfl (no smem, no barrier) ---- */
#pragma unroll
        for (int j = 0; j < 16; j++) {
            int src = (lane & 16) | j;
            const float* vp = &sVb[j * KSTR + oc0];
            ulonglong2 v0 = *(const ulonglong2*)&vp[0];
            ulonglong2 v1 = *(const ulonglong2*)&vp[4];
#pragma unroll
            for (int i = 0; i < 4; i++) {
                u64 p2 = pack2(__shfl_sync(0xffffffffu, pA[i], src, 32));
                fma2(oacc[i][0], p2, v0.x);
                fma2(oacc[i][1], p2, v0.y);
                fma2(oacc[i][2], p2, v1.x);
                fma2(oacc[i][3], p2, v1.y);
            }
        }
#pragma unroll
        for (int j = 0; j < 16; j++) {
            int src = (lane & 16) | j;
            const float* vp = &sVb[(j + 16) * KSTR + oc0];
            ulonglong2 v0 = *(const ulonglong2*)&vp[0];
            ulonglong2 v1 = *(const ulonglong2*)&vp[4];
#pragma unroll
            for (int i = 0; i < 4; i++) {
                u64 p2 = pack2(__shfl_sync(0xffffffffu, pB[i], src, 32));
                fma2(oacc[i][0], p2, v0.x);
                fma2(oacc[i][1], p2, v0.y);
                fma2(oacc[i][2], p2, v1.x);
                fma2(oacc[i][3], p2, v1.y);
            }
        }
    }

    /* ---- epilogue: partial O and (m,l) ---- */
#pragma unroll
    for (int i = 0; i < 4; i++) {
        int r = r0 + i;
        size_t base = (((size_t)b * 64 + r) * NSPLIT + s) * HD + oc0;
        float2 f0 = unpk(oacc[i][0]), f1 = unpk(oacc[i][1]);
        float2 f2 = unpk(oacc[i][2]), f3 = unpk(oacc[i][3]);
        *(float4*)&g_po[base]     = make_float4(f0.x, f0.y, f1.x, f1.y);
        *(float4*)&g_po[base + 4] = make_float4(f2.x, f2.y, f3.x, f3.y);
    }
    if (stx == 0) {
#pragma unroll
        for (int i = 0; i < 4; i++) {
            size_t pb = (((size_t)b * 64 + r0 + i) * NSPLIT + s) * 2;
            g_pml[pb]     = mreg[i];
            g_pml[pb + 1] = lreg[i];
        }
    }
}

/* ------------------------------------------------------------------ */
/* Combine the NSPLIT partial softmax results                          */
/* ------------------------------------------------------------------ */
__global__ void combine_kernel()
{
    int b = blockIdx.x, tid = threadIdx.x;
    int r = tid >> 2, e0 = (tid & 3) * 32;
    size_t pbase = ((size_t)b * 64 + r) * NSPLIT;

    float ms[NSPLIT], ls[NSPLIT], w[NSPLIT];
    float M = -1e30f;
#pragma unroll
    for (int s = 0; s < NSPLIT; s++) {
        ms[s] = g_pml[(pbase + s) * 2];
        ls[s] = g_pml[(pbase + s) * 2 + 1];
        M = fmaxf(M, ms[s]);
    }
    float L = 0.f;
#pragma unroll
    for (int s = 0; s < NSPLIT; s++) { w[s] = __expf(ms[s] - M); L += ls[s] * w[s]; }
    float inv = 1.f / L;
#pragma unroll
    for (int s = 0; s < NSPLIT; s++) w[s] *= inv;

    int q = r & 3, h = r >> 2;
    float* dst = g_o + (size_t)(b * QL + q) * DIM + h * HD;
    for (int e = e0; e < e0 + 32; e += 4) {
        float4 acc = make_float4(0.f, 0.f, 0.f, 0.f);
#pragma unroll
        for (int s = 0; s < NSPLIT; s++) {
            float4 v = *(const float4*)&g_po[(pbase + s) * HD + e];
            acc.x += v.x * w[s]; acc.y += v.y * w[s];
            acc.z += v.z * w[s]; acc.w += v.w * w[s];
        }
        *(float4*)&dst[e] = acc;
    }
}

/* ------------------------------------------------------------------ */
/* Reduce split-K partials for output projection + bo -> d_out         */
/* ------------------------------------------------------------------ */
__global__ void reduce_out(const float* __restrict__ bo, float* __restrict__ out)
{
    int idx = blockIdx.x * 256 + threadIdx.x;
    int m = idx >> 9;
    int n = (idx & 511) << 2;
    float4 s = *(const float4*)&bo[n];
#pragma unroll
    for (int sk = 0; sk < NSPLIT; sk++) {
        float4 v = *(const float4*)&g_part[(size_t)(sk * M_ + m) * NQKV + n];
        s.x += v.x; s.y += v.y; s.z += v.z; s.w += v.w;
    }
    *(float4*)&out[(size_t)m * DIM + n] = s;
}

/* ------------------------------------------------------------------ */
extern "C" void kernel_launch(void* const* d_in, const int* in_sizes, int n_in,
                              void* d_out, int out_size)
{
    const float* x         = (const float*)d_in[0];
    const float* attn_bias = (const float*)d_in[1];
    const float* cache_k   = (const float*)d_in[2];
    const float* cache_v   = (const float*)d_in[3];
    const float* wq        = (const float*)d_in[4];
    const float* bq        = (const float*)d_in[5];
    const float* wk        = (const float*)d_in[6];
    const float* bk        = (const float*)d_in[7];
    const float* wv        = (const float*)d_in[8];
    const float* bv        = (const float*)d_in[9];
    const float* wo        = (const float*)d_in[10];
    const float* bo        = (const float*)d_in[11];
    float*       out       = (float*)d_out;

    cudaFuncSetAttribute(attn_kernel,
                         cudaFuncAttributeMaxDynamicSharedMemorySize, ATTN_SMEM);

    float* go_ptr = nullptr;
    cudaGetSymbolAddress((void**)&go_ptr, g_o);

    /* 1) QKV projections (split-K) */
    gemm64<<<dim3(32, 2, NSPLIT), 256>>>(x, DIM, wq, 2048, 0);
    gemm64<<<dim3(2, 2, NSPLIT), 256>>>(x, DIM, wk, 128, 2048);
    gemm64<<<dim3(2, 2, NSPLIT), 256>>>(x, DIM, wv, 128, 2176);
    reduce_qkv<<<288, 256>>>(bq, bk, bv);

    /* 2) fused flash attention, split over KV */
    attn_kernel<<<dim3(NSPLIT, B_), 256, ATTN_SMEM>>>(attn_bias, cache_k, cache_v);

    /* 3) combine split-softmax partials */
    combine_kernel<<<B_, 256>>>();

    /* 4) output projection (split-K) */
    gemm64<<<dim3(32, 2, NSPLIT), 256>>>(go_ptr, DIM, wo, DIM, 0);
    reduce_out<<<256, 256>>>(bo, out);
}

// round 8
// speedup vs baseline: 1.1542x; 1.0794x over previous
#include <cuda_runtime.h>
#include <cstdint>

typedef unsigned long long u64;

#define B_      32
#define QL      4
#define DIM     2048
#define HEADS   16
#define HD      128
#define KVL     8192
#define M_      (B_*QL)          /* 128 rows for projection GEMMs        */
#define NQKV    2304             /* 2048 q-cols + 128 k + 128 v          */
#define NSPLIT  8
#define CHUNK   (KVL/NSPLIT)     /* 1024 keys per attention block        */
#define NT      (CHUNK/32)       /* 32-key subtiles per block            */
#define SCALE   0.08838834764831845f

/* ------------------------------------------------------------------ */
/* scratch (device globals — no allocations allowed)                   */
/* ------------------------------------------------------------------ */
__device__ float g_part[NSPLIT * M_ * NQKV];            /* split-K partials (both GEMMs) */
__device__ float g_qkv [M_ * NQKV];                     /* q | k_new | v_new             */
__device__ float g_po  [(size_t)B_ * 64 * NSPLIT * HD]; /* partial O per KV split        */
__device__ float g_pml [B_ * 64 * NSPLIT * 2];          /* partial (m, l)                */
__device__ float g_o   [M_ * DIM];                      /* combined attention output     */

/* ------------------------------------------------------------------ */
/* packed f32x2 helpers (Blackwell-only FFMA2 path)                    */
/* ------------------------------------------------------------------ */
__device__ __forceinline__ u64 pack2(float x) {
    u64 r; asm("mov.b64 %0, {%1, %1};" : "=l"(r) : "f"(x)); return r;
}
__device__ __forceinline__ void fma2(u64& d, u64 a, u64 b) {
    asm("fma.rn.f32x2 %0, %1, %2, %0;" : "+l"(d) : "l"(a), "l"(b));
}
__device__ __forceinline__ void mul2(u64& d, u64 a) {
    asm("mul.rn.f32x2 %0, %0, %1;" : "+l"(d) : "l"(a));
}
__device__ __forceinline__ float2 unpk(u64 v) {
    float2 f; asm("mov.b64 {%0, %1}, %2;" : "=f"(f.x), "=f"(f.y) : "l"(v)); return f;
}
__device__ __forceinline__ void cp16(uint32_t saddr, const void* g) {
    asm volatile("cp.async.cg.shared.global [%0], [%1], 16;" :: "r"(saddr), "l"(g));
}
#define CP_COMMIT() asm volatile("cp.async.commit_group;")
#define CP_WAIT0()  asm volatile("cp.async.wait_group 0;")
#define CP_WAIT1()  asm volatile("cp.async.wait_group 1;")

/* ------------------------------------------------------------------ */
/* Kernel: split-K GEMM, 64x64 tile, K-chunk 256 per blockIdx.z        */
/* ------------------------------------------------------------------ */
__global__ __launch_bounds__(256) void gemm64(
    const float* __restrict__ A, int lda,
    const float* __restrict__ B, int ldb,
    int ncol0)
{
    __shared__ u64   sA2[16][65];
    __shared__ float sB[16][64];

    const int tid = threadIdx.x;
    const int tx  = tid & 15, ty = tid >> 4;
    const int m0  = blockIdx.y * 64, n0 = blockIdx.x * 64;
    const int k0  = blockIdx.z * 256;

    u64 acc[4][2];
#pragma unroll
    for (int i = 0; i < 4; i++) { acc[i][0] = 0ull; acc[i][1] = 0ull; }

    const int ar = tid >> 2, akq = tid & 3;
    const int bk = tid >> 4, bc  = tid & 15;

    for (int kt = 0; kt < 256; kt += 16) {
        float4 av = *(const float4*)&A[(size_t)(m0 + ar) * lda + k0 + kt + akq * 4];
        float4 bv = *(const float4*)&B[(size_t)(k0 + kt + bk) * ldb + n0 + bc * 4];
        __syncthreads();
        sA2[akq * 4 + 0][ar] = pack2(av.x);
        sA2[akq * 4 + 1][ar] = pack2(av.y);
        sA2[akq * 4 + 2][ar] = pack2(av.z);
        sA2[akq * 4 + 3][ar] = pack2(av.w);
        *(float4*)&sB[bk][bc * 4] = bv;
        __syncthreads();
#pragma unroll
        for (int kk = 0; kk < 16; kk++) {
            ulonglong2 b2 = *(const ulonglong2*)&sB[kk][tx * 4];
#pragma unroll
            for (int i = 0; i < 4; i++) {
                u64 a2 = sA2[kk][ty * 4 + i];
                fma2(acc[i][0], a2, b2.x);
                fma2(acc[i][1], a2, b2.y);
            }
        }
    }

    float* dst = g_part + (size_t)(blockIdx.z * M_ + m0) * NQKV + ncol0 + n0;
#pragma unroll
    for (int i = 0; i < 4; i++) {
        float2 f0 = unpk(acc[i][0]), f1 = unpk(acc[i][1]);
        float4 o4 = make_float4(f0.x, f0.y, f1.x, f1.y);
        *(float4*)&dst[(size_t)(ty * 4 + i) * NQKV + tx * 4] = o4;
    }
}

/* ------------------------------------------------------------------ */
/* Reduce split-K partials for QKV projection, add biases             */
/* ------------------------------------------------------------------ */
__global__ void reduce_qkv(const float* __restrict__ bq,
                           const float* __restrict__ bk,
                           const float* __restrict__ bv)
{
    int idx = blockIdx.x * 256 + threadIdx.x;
    if (idx >= M_ * NQKV / 4) return;
    int m = idx / (NQKV / 4);
    int n = (idx % (NQKV / 4)) * 4;
    float4 s = make_float4(0.f, 0.f, 0.f, 0.f);
#pragma unroll
    for (int sk = 0; sk < NSPLIT; sk++) {
        float4 v = *(const float4*)&g_part[(size_t)(sk * M_ + m) * NQKV + n];
        s.x += v.x; s.y += v.y; s.z += v.z; s.w += v.w;
    }
    float4 bb;
    if (n < 2048)       bb = *(const float4*)&bq[n];
    else if (n < 2176)  bb = *(const float4*)&bk[n - 2048];
    else                bb = *(const float4*)&bv[n - 2176];
    s.x += bb.x; s.y += bb.y; s.z += bb.z; s.w += bb.w;
    *(float4*)&g_qkv[(size_t)m * NQKV + n] = s;
}

/* ------------------------------------------------------------------ */
/* Fused flash attention v3                                            */
/*   - 2 blocks/SM enforced (regs<=128, smem ~98.5KB)                  */
/*   - K double-buffered (wait_group 1), V single-buffered             */
/*   - P staged in smem pre-packed f32x2 (warp-private, syncwarp only) */
/*   - conflict-free V reads via LDS.64 at cols 2*stx + 32*cidx        */
/* grid = (NSPLIT, B); 256 threads                                     */
/* ------------------------------------------------------------------ */
#define QSTR 128
#define KSTR 132
#define SQ_ELEMS (64 * QSTR)                 /* 8192 floats  */
#define KV_ELEMS (32 * KSTR)                 /* 4224 floats  */
#define PSTRIDE  34                          /* u64 elements per row */
#define SP_U64   (64 * PSTRIDE)              /* 2176 u64     */
/* float-offset layout: sQ | sK(2 bufs) | sV(1 buf) | sP */
#define OFF_K    SQ_ELEMS
#define OFF_V    (OFF_K + 2 * KV_ELEMS)
#define OFF_P    (OFF_V + KV_ELEMS)          /* 20864 floats, 16B aligned */
#define ATTN_SMEM ((OFF_P + SP_U64 * 2) * 4)

__global__ __launch_bounds__(256, 2) void attn_kernel(
    const float* __restrict__ bias,
    const float* __restrict__ cache_k,
    const float* __restrict__ cache_v)
{
    extern __shared__ float sm[];
    float* sQ = sm;
    float* sK = sm + OFF_K;
    float* sV = sm + OFF_V;
    u64*   sP = (u64*)(sm + OFF_P);

    const int tid  = threadIdx.x;
    const int s    = blockIdx.x;
    const int b    = blockIdx.y;

    const int stx = tid & 15;            /* key lane / col group       */
    const int r0  = (tid >> 4) * 4;      /* 4 rows per thread          */

    const uint32_t skb = (uint32_t)__cvta_generic_to_shared(sK);
    const uint32_t svb = (uint32_t)__cvta_generic_to_shared(sV);

    const int kb0 = s * CHUNK;

    /* load Q tile (rows r = h*4+q) */
    for (int idx = tid; idx < 64 * 32; idx += 256) {
        int r = idx >> 5, c4 = (idx & 31) << 2;
        int q = r & 3, h = r >> 2;
        *(float4*)&sQ[r * QSTR + c4] =
            *(const float4*)&g_qkv[(size_t)(b * QL + q) * NQKV + h * HD + c4];
    }

    /* prologue: issue K(0) and V(0) as one group */
#pragma unroll
    for (int k = 0; k < 4; k++) {
        int idx = tid + k * 256;
        int jr = idx >> 5, c4 = (idx & 31) << 2;
        int jg = kb0 + jr;
        const float *srck, *srcv;
        if (jg < KVL - QL) {
            size_t off = ((size_t)b * KVL + jg + QL) * HD + c4;
            srck = cache_k + off; srcv = cache_v + off;
        } else {
            size_t mrow = (size_t)(b * QL + (jg - (KVL - QL))) * NQKV;
            srck = g_qkv + mrow + 2048 + c4;
            srcv = g_qkv + mrow + 2176 + c4;
        }
        uint32_t so = (uint32_t)((jr * KSTR + c4) * 4);
        cp16(skb + so, srck);
        cp16(svb + so, srcv);
    }
    CP_COMMIT();

    float mreg[4], lreg[4];
#pragma unroll
    for (int i = 0; i < 4; i++) { mreg[i] = -1e30f; lreg[i] = 0.f; }

    u64 oacc[4][4];                      /* [row][cidx]: cols 2*stx+32*cidx */
#pragma unroll
    for (int i = 0; i < 4; i++)
#pragma unroll
        for (int c = 0; c < 4; c++) oacc[i][c] = 0ull;

    const float* bptr = bias + ((size_t)b * 64 + r0) * KVL + kb0 + stx;

    for (int t = 0; t < NT; t++) {
        /* prefetch K(t+1) into the other K buffer, then drain K(t),V(t) */
        if (t + 1 < NT) {
            int tn = t + 1;
            uint32_t kdst = skb + (uint32_t)(tn & 1) * (KV_ELEMS * 4);
#pragma unroll
            for (int k = 0; k < 4; k++) {
                int idx = tid + k * 256;
                int jr = idx >> 5, c4 = (idx & 31) << 2;
                int jg = kb0 + tn * 32 + jr;
                const float* srck;
                if (jg < KVL - QL)
                    srck = cache_k + ((size_t)b * KVL + jg + QL) * HD + c4;
                else
                    srck = g_qkv + (size_t)(b * QL + (jg - (KVL - QL))) * NQKV + 2048 + c4;
                cp16(kdst + (uint32_t)((jr * KSTR + c4) * 4), srck);
            }
            CP_COMMIT();
            CP_WAIT1();
        } else {
            CP_WAIT0();
        }
        __syncthreads();                 /* K(t),V(t) visible to all */

        /* bias for this tile straight from gmem (single touch) */
        float bA[4], bB[4];
#pragma unroll
        for (int i = 0; i < 4; i++) {
            bA[i] = bptr[(size_t)i * KVL + t * 32];
            bB[i] = bptr[(size_t)i * KVL + t * 32 + 16];
        }

        const float* sKb = sK + (t & 1) * KV_ELEMS;

        /* ---- S = Q K^T (f32x2 over e), kept in registers ---- */
        u64 accA[4], accB[4];
#pragma unroll
        for (int i = 0; i < 4; i++) { accA[i] = 0ull; accB[i] = 0ull; }
        {
            const float* kp0 = &sKb[stx * KSTR];
            const float* kp1 = &sKb[(stx + 16) * KSTR];
#pragma unroll 4
            for (int e = 0; e < 128; e += 4) {
                ulonglong2 kA = *(const ulonglong2*)&kp0[e];
                ulonglong2 kB = *(const ulonglong2*)&kp1[e];
#pragma unroll
                for (int i = 0; i < 4; i++) {
                    ulonglong2 qv = *(const ulonglong2*)&sQ[(r0 + i) * QSTR + e];
                    fma2(accA[i], qv.x, kA.x); fma2(accA[i], qv.y, kA.y);
                    fma2(accB[i], qv.x, kB.x); fma2(accB[i], qv.y, kB.y);
                }
            }
        }

        /* ---- online softmax: half-warp shfl reductions ---- */
#pragma unroll
        for (int i = 0; i < 4; i++) {
            float2 a = unpk(accA[i]);
            float2 c = unpk(accB[i]);
            float vA = (a.x + a.y) * SCALE + bA[i];
            float vB = (c.x + c.y) * SCALE + bB[i];
            float mx = fmaxf(vA, vB);
            mx = fmaxf(mx, __shfl_xor_sync(0xffffffffu, mx, 8, 16));
            mx = fmaxf(mx, __shfl_xor_sync(0xffffffffu, mx, 4, 16));
            mx = fmaxf(mx, __shfl_xor_sync(0xffffffffu, mx, 2, 16));
            mx = fmaxf(mx, __shfl_xor_sync(0xffffffffu, mx, 1, 16));
            float mn = fmaxf(mreg[i], mx);
            float al = __expf(mreg[i] - mn);
            float pa = __expf(vA - mn);
            float pb = __expf(vB - mn);
            float ls = pa + pb;
            ls += __shfl_xor_sync(0xffffffffu, ls, 8, 16);
            ls += __shfl_xor_sync(0xffffffffu, ls, 4, 16);
            ls += __shfl_xor_sync(0xffffffffu, ls, 2, 16);
            ls += __shfl_xor_sync(0xffffffffu, ls, 1, 16);
            lreg[i] = lreg[i] * al + ls;
            mreg[i] = mn;
            /* stage P pre-packed (warp-private rows) */
            sP[(r0 + i) * PSTRIDE + stx]      = pack2(pa);
            sP[(r0 + i) * PSTRIDE + stx + 16] = pack2(pb);
            u64 a2 = pack2(al);
            mul2(oacc[i][0], a2); mul2(oacc[i][1], a2);
            mul2(oacc[i][2], a2); mul2(oacc[i][3], a2);
        }
        __syncwarp();

        /* ---- O += P V : P pairs from smem, conflict-free V LDS.64 ---- */
        {
            const int c0 = 2 * stx;      /* cols c0+32*cidx, +1 */
#pragma unroll 4
            for (int j2 = 0; j2 < 16; j2++) {
                const float* vp0 = &sV[(2 * j2) * KSTR + c0];
                const float* vp1 = &sV[(2 * j2 + 1) * KSTR + c0];
                u64 v00 = *(const u64*)&vp0[0];
                u64 v01 = *(const u64*)&vp0[32];
                u64 v02 = *(const u64*)&vp0[64];
                u64 v03 = *(const u64*)&vp0[96];
                u64 v10 = *(const u64*)&vp1[0];
                u64 v11 = *(const u64*)&vp1[32];
                u64 v12 = *(const u64*)&vp1[64];
                u64 v13 = *(const u64*)&vp1[96];
#pragma unroll
                for (int i = 0; i < 4; i++) {
                    ulonglong2 pp = *(const ulonglong2*)&sP[(r0 + i) * PSTRIDE + 2 * j2];
                    fma2(oacc[i][0], pp.x, v00);
                    fma2(oacc[i][1], pp.x, v01);
                    fma2(oacc[i][2], pp.x, v02);
                    fma2(oacc[i][3], pp.x, v03);
                    fma2(oacc[i][0], pp.y, v10);
                    fma2(oacc[i][1], pp.y, v11);
                    fma2(oacc[i][2], pp.y, v12);
                    fma2(oacc[i][3], pp.y, v13);
                }
            }
        }

        /* V(t+1) into the single V buffer (after everyone is done with V(t)) */
        __syncthreads();
        if (t + 1 < NT) {
            int tn = t + 1;
#pragma unroll
            for (int k = 0; k < 4; k++) {
                int idx = tid + k * 256;
                int jr = idx >> 5, c4 = (idx & 31) << 2;
                int jg = kb0 + tn * 32 + jr;
                const float* srcv;
                if (jg < KVL - QL)
                    srcv = cache_v + ((size_t)b * KVL + jg + QL) * HD + c4;
                else
                    srcv = g_qkv + (size_t)(b * QL + (jg - (KVL - QL))) * NQKV + 2176 + c4;
                cp16(svb + (uint32_t)((jr * KSTR + c4) * 4), srcv);
            }
            CP_COMMIT();
        }
    }

    /* ---- epilogue: partial O (cols 2*stx+32*cidx) and (m,l) ---- */
#pragma unroll
    for (int i = 0; i < 4; i++) {
        int r = r0 + i;
        size_t base = (((size_t)b * 64 + r) * NSPLIT + s) * HD + 2 * stx;
#pragma unroll
        for (int c = 0; c < 4; c++) {
            float2 f = unpk(oacc[i][c]);
            *(float2*)&g_po[base + 32 * c] = f;
        }
    }
    if (stx == 0) {
#pragma unroll
        for (int i = 0; i < 4; i++) {
            size_t pb = (((size_t)b * 64 + r0 + i) * NSPLIT + s) * 2;
            g_pml[pb]     = mreg[i];
            g_pml[pb + 1] = lreg[i];
        }
    }
}

/* ------------------------------------------------------------------ */
/* Combine the NSPLIT partial softmax results                          */
/* ------------------------------------------------------------------ */
__global__ void combine_kernel()
{
    int b = blockIdx.x, tid = threadIdx.x;
    int r = tid >> 2, e0 = (tid & 3) * 32;
    size_t pbase = ((size_t)b * 64 + r) * NSPLIT;

    float ms[NSPLIT], ls[NSPLIT], w[NSPLIT];
    float M = -1e30f;
#pragma unroll
    for (int s = 0; s < NSPLIT; s++) {
        ms[s] = g_pml[(pbase + s) * 2];
        ls[s] = g_pml[(pbase + s) * 2 + 1];
        M = fmaxf(M, ms[s]);
    }
    float L = 0.f;
#pragma unroll
    for (int s = 0; s < NSPLIT; s++) { w[s] = __expf(ms[s] - M); L += ls[s] * w[s]; }
    float inv = 1.f / L;
#pragma unroll
    for (int s = 0; s < NSPLIT; s++) w[s] *= inv;

    int q = r & 3, h = r >> 2;
    float* dst = g_o + (size_t)(b * QL + q) * DIM + h * HD;
    for (int e = e0; e < e0 + 32; e += 4) {
        float4 acc = make_float4(0.f, 0.f, 0.f, 0.f);
#pragma unroll
        for (int s = 0; s < NSPLIT; s++) {
            float4 v = *(const float4*)&g_po[(pbase + s) * HD + e];
            acc.x += v.x * w[s]; acc.y += v.y * w[s];
            acc.z += v.z * w[s]; acc.w += v.w * w[s];
        }
        *(float4*)&dst[e] = acc;
    }
}

/* ------------------------------------------------------------------ */
/* Reduce split-K partials for output projection + bo -> d_out         */
/* ------------------------------------------------------------------ */
__global__ void reduce_out(const float* __restrict__ bo, float* __restrict__ out)
{
    int idx = blockIdx.x * 256 + threadIdx.x;
    int m = idx >> 9;
    int n = (idx & 511) << 2;
    float4 s = *(const float4*)&bo[n];
#pragma unroll
    for (int sk = 0; sk < NSPLIT; sk++) {
        float4 v = *(const float4*)&g_part[(size_t)(sk * M_ + m) * NQKV + n];
        s.x += v.x; s.y += v.y; s.z += v.z; s.w += v.w;
    }
    *(float4*)&out[(size_t)m * DIM + n] = s;
}

/* ------------------------------------------------------------------ */
extern "C" void kernel_launch(void* const* d_in, const int* in_sizes, int n_in,
                              void* d_out, int out_size)
{
    const float* x         = (const float*)d_in[0];
    const float* attn_bias = (const float*)d_in[1];
    const float* cache_k   = (const float*)d_in[2];
    const float* cache_v   = (const float*)d_in[3];
    const float* wq        = (const float*)d_in[4];
    const float* bq        = (const float*)d_in[5];
    const float* wk        = (const float*)d_in[6];
    const float* bk        = (const float*)d_in[7];
    const float* wv        = (const float*)d_in[8];
    const float* bv        = (const float*)d_in[9];
    const float* wo        = (const float*)d_in[10];
    const float* bo        = (const float*)d_in[11];
    float*       out       = (float*)d_out;

    cudaFuncSetAttribute(attn_kernel,
                         cudaFuncAttributeMaxDynamicSharedMemorySize, ATTN_SMEM);

    float* go_ptr = nullptr;
    cudaGetSymbolAddress((void**)&go_ptr, g_o);

    /* 1) QKV projections (split-K) */
    gemm64<<<dim3(32, 2, NSPLIT), 256>>>(x, DIM, wq, 2048, 0);
    gemm64<<<dim3(2, 2, NSPLIT), 256>>>(x, DIM, wk, 128, 2048);
    gemm64<<<dim3(2, 2, NSPLIT), 256>>>(x, DIM, wv, 128, 2176);
    reduce_qkv<<<288, 256>>>(bq, bk, bv);

    /* 2) fused flash attention, split over KV */
    attn_kernel<<<dim3(NSPLIT, B_), 256, ATTN_SMEM>>>(attn_bias, cache_k, cache_v);

    /* 3) combine split-softmax partials */
    combine_kernel<<<B_, 256>>>();

    /* 4) output projection (split-K) */
    gemm64<<<dim3(32, 2, NSPLIT), 256>>>(go_ptr, DIM, wo, DIM, 0);
    reduce_out<<<256, 256>>>(bo, out);
}

// round 9
// speedup vs baseline: 1.2298x; 1.0655x over previous
#include <cuda_runtime.h>
#include <cstdint>

typedef unsigned long long u64;

#define B_      32
#define QL      4
#define DIM     2048
#define HEADS   16
#define HD      128
#define KVL     8192
#define M_      (B_*QL)          /* 128 rows for projection GEMMs        */
#define NQKV    2304             /* 2048 q-cols + 128 k + 128 v          */
#define NSPLIT  8
#define CHUNK   (KVL/NSPLIT)     /* 1024 keys per attention block        */
#define NT      (CHUNK/32)       /* 32-key subtiles per block            */
#define SCALE   0.08838834764831845f

/* ------------------------------------------------------------------ */
/* scratch (device globals — no allocations allowed)                   */
/* ------------------------------------------------------------------ */
__device__ float g_part[NSPLIT * M_ * NQKV];            /* split-K partials (both GEMMs) */
__device__ float g_qkv [M_ * NQKV];                     /* q | k_new | v_new             */
__device__ float g_po  [(size_t)B_ * 64 * NSPLIT * HD]; /* partial O per KV split        */
__device__ float g_pml [B_ * 64 * NSPLIT * 2];          /* partial (m, l)                */
__device__ float g_o   [M_ * DIM];                      /* combined attention output     */

/* ------------------------------------------------------------------ */
/* packed f32x2 helpers (Blackwell-only FFMA2 path)                    */
/* ------------------------------------------------------------------ */
__device__ __forceinline__ u64 pack2(float x) {
    u64 r; asm("mov.b64 %0, {%1, %1};" : "=l"(r) : "f"(x)); return r;
}
__device__ __forceinline__ void fma2(u64& d, u64 a, u64 b) {
    asm("fma.rn.f32x2 %0, %1, %2, %0;" : "+l"(d) : "l"(a), "l"(b));
}
__device__ __forceinline__ void mul2(u64& d, u64 a) {
    asm("mul.rn.f32x2 %0, %0, %1;" : "+l"(d) : "l"(a));
}
__device__ __forceinline__ float2 unpk(u64 v) {
    float2 f; asm("mov.b64 {%0, %1}, %2;" : "=f"(f.x), "=f"(f.y) : "l"(v)); return f;
}
__device__ __forceinline__ void cp16(uint32_t saddr, const void* g) {
    asm volatile("cp.async.cg.shared.global [%0], [%1], 16;" :: "r"(saddr), "l"(g));
}
#define CP_COMMIT() asm volatile("cp.async.commit_group;")
#define CP_WAIT0()  asm volatile("cp.async.wait_group 0;")
#define CP_WAIT1()  asm volatile("cp.async.wait_group 1;")

/* ------------------------------------------------------------------ */
/* Kernel: split-K GEMM, 64x64 tile, K-chunk 256 per blockIdx.z        */
/* ------------------------------------------------------------------ */
__global__ __launch_bounds__(256) void gemm64(
    const float* __restrict__ A, int lda,
    const float* __restrict__ B, int ldb,
    int ncol0)
{
    __shared__ u64   sA2[16][65];
    __shared__ float sB[16][64];

    const int tid = threadIdx.x;
    const int tx  = tid & 15, ty = tid >> 4;
    const int m0  = blockIdx.y * 64, n0 = blockIdx.x * 64;
    const int k0  = blockIdx.z * 256;

    u64 acc[4][2];
#pragma unroll
    for (int i = 0; i < 4; i++) { acc[i][0] = 0ull; acc[i][1] = 0ull; }

    const int ar = tid >> 2, akq = tid & 3;
    const int bk = tid >> 4, bc  = tid & 15;

    for (int kt = 0; kt < 256; kt += 16) {
        float4 av = *(const float4*)&A[(size_t)(m0 + ar) * lda + k0 + kt + akq * 4];
        float4 bv = *(const float4*)&B[(size_t)(k0 + kt + bk) * ldb + n0 + bc * 4];
        __syncthreads();
        sA2[akq * 4 + 0][ar] = pack2(av.x);
        sA2[akq * 4 + 1][ar] = pack2(av.y);
        sA2[akq * 4 + 2][ar] = pack2(av.z);
        sA2[akq * 4 + 3][ar] = pack2(av.w);
        *(float4*)&sB[bk][bc * 4] = bv;
        __syncthreads();
#pragma unroll
        for (int kk = 0; kk < 16; kk++) {
            ulonglong2 b2 = *(const ulonglong2*)&sB[kk][tx * 4];
#pragma unroll
            for (int i = 0; i < 4; i++) {
                u64 a2 = sA2[kk][ty * 4 + i];
                fma2(acc[i][0], a2, b2.x);
                fma2(acc[i][1], a2, b2.y);
            }
        }
    }

    float* dst = g_part + (size_t)(blockIdx.z * M_ + m0) * NQKV + ncol0 + n0;
#pragma unroll
    for (int i = 0; i < 4; i++) {
        float2 f0 = unpk(acc[i][0]), f1 = unpk(acc[i][1]);
        float4 o4 = make_float4(f0.x, f0.y, f1.x, f1.y);
        *(float4*)&dst[(size_t)(ty * 4 + i) * NQKV + tx * 4] = o4;
    }
}

/* ------------------------------------------------------------------ */
/* Reduce split-K partials for QKV projection, add biases             */
/* ------------------------------------------------------------------ */
__global__ void reduce_qkv(const float* __restrict__ bq,
                           const float* __restrict__ bk,
                           const float* __restrict__ bv)
{
    int idx = blockIdx.x * 256 + threadIdx.x;
    if (idx >= M_ * NQKV / 4) return;
    int m = idx / (NQKV / 4);
    int n = (idx % (NQKV / 4)) * 4;
    float4 s = make_float4(0.f, 0.f, 0.f, 0.f);
#pragma unroll
    for (int sk = 0; sk < NSPLIT; sk++) {
        float4 v = *(const float4*)&g_part[(size_t)(sk * M_ + m) * NQKV + n];
        s.x += v.x; s.y += v.y; s.z += v.z; s.w += v.w;
    }
    float4 bb;
    if (n < 2048)       bb = *(const float4*)&bq[n];
    else if (n < 2176)  bb = *(const float4*)&bk[n - 2048];
    else                bb = *(const float4*)&bv[n - 2176];
    s.x += bb.x; s.y += bb.y; s.z += bb.z; s.w += bb.w;
    *(float4*)&g_qkv[(size_t)m * NQKV + n] = s;
}

/* ------------------------------------------------------------------ */
/* Fused flash attention v4                                            */
/*   - K AND V double-buffered, combined group, 1-iter lookahead       */
/*   - bias prefetched one tile ahead into registers                   */
/*   - P staged as floats (stride 34), broadcast reads + reg packing   */
/*   - 2 blocks/SM (smem ~105.3KB, regs <=128)                         */
/* grid = (NSPLIT, B); 256 threads                                     */
/* ------------------------------------------------------------------ */
#define QSTR  128
#define KSTR  132
#define VSTR  128
#define SQ_ELEMS (64 * QSTR)                 /* 8192 floats */
#define K_ELEMS  (32 * KSTR)                 /* 4224 floats */
#define V_ELEMS  (32 * VSTR)                 /* 4096 floats */
#define PSTR  34                             /* floats per P row */
#define OFF_K    SQ_ELEMS
#define OFF_V    (OFF_K + 2 * K_ELEMS)
#define OFF_P    (OFF_V + 2 * V_ELEMS)
#define ATTN_SMEM ((OFF_P + 64 * PSTR) * 4)  /* 107776 B */

__global__ __launch_bounds__(256, 2) void attn_kernel(
    const float* __restrict__ bias,
    const float* __restrict__ cache_k,
    const float* __restrict__ cache_v)
{
    extern __shared__ float sm[];
    float* sQ  = sm;
    float* sK  = sm + OFF_K;
    float* sV  = sm + OFF_V;
    float* sPf = sm + OFF_P;

    const int tid  = threadIdx.x;
    const int s    = blockIdx.x;
    const int b    = blockIdx.y;

    const int stx = tid & 15;            /* key lane / col group       */
    const int r0  = (tid >> 4) * 4;      /* 4 rows per thread          */

    const uint32_t skb = (uint32_t)__cvta_generic_to_shared(sK);
    const uint32_t svb = (uint32_t)__cvta_generic_to_shared(sV);

    const int kb0 = s * CHUNK;

    /* per-thread K/V load map: idx = tid + k*256 -> jr = idx>>5, c4 = (idx&31)<<2 */
    const int jr_[4] = { tid >> 5,            (tid + 256) >> 5,
                         (tid + 512) >> 5,    (tid + 768) >> 5 };
    const int c4v   = (tid & 31) << 2;

    /* load Q tile (rows r = h*4+q) */
    for (int idx = tid; idx < 64 * 32; idx += 256) {
        int r = idx >> 5, c4 = (idx & 31) << 2;
        int q = r & 3, h = r >> 2;
        *(float4*)&sQ[r * QSTR + c4] =
            *(const float4*)&g_qkv[(size_t)(b * QL + q) * NQKV + h * HD + c4];
    }

    /* prologue: issue K(0)+V(0) as one group */
#pragma unroll
    for (int k = 0; k < 4; k++) {
        int jr = jr_[k];
        int jg = kb0 + jr;
        const float *srck, *srcv;
        if (jg < KVL - QL) {
            size_t off = ((size_t)b * KVL + jg + QL) * HD + c4v;
            srck = cache_k + off; srcv = cache_v + off;
        } else {
            size_t mrow = (size_t)(b * QL + (jg - (KVL - QL))) * NQKV;
            srck = g_qkv + mrow + 2048 + c4v;
            srcv = g_qkv + mrow + 2176 + c4v;
        }
        cp16(skb + (uint32_t)((jr * KSTR + c4v) * 4), srck);
        cp16(svb + (uint32_t)((jr * VSTR + c4v) * 4), srcv);
    }
    CP_COMMIT();

    const float* bptr = bias + ((size_t)b * 64 + r0) * KVL + kb0 + stx;

    /* prologue: bias(0) into registers */
    float bA_n[4], bB_n[4];
#pragma unroll
    for (int i = 0; i < 4; i++) {
        bA_n[i] = bptr[(size_t)i * KVL];
        bB_n[i] = bptr[(size_t)i * KVL + 16];
    }

    float mreg[4], lreg[4];
#pragma unroll
    for (int i = 0; i < 4; i++) { mreg[i] = -1e30f; lreg[i] = 0.f; }

    u64 oacc[4][4];                      /* [row][cidx]: cols 2*stx+32*cidx */
#pragma unroll
    for (int i = 0; i < 4; i++)
#pragma unroll
        for (int c = 0; c < 4; c++) oacc[i][c] = 0ull;

    for (int t = 0; t < NT; t++) {
        __syncthreads();                 /* all warps done with iter t-1:
                                            buffer (t+1)&1 is dead, sP free */

        /* consume prefetched bias; prefetch bias(t+1) */
        float bA[4], bB[4];
#pragma unroll
        for (int i = 0; i < 4; i++) { bA[i] = bA_n[i]; bB[i] = bB_n[i]; }
        if (t + 1 < NT) {
#pragma unroll
            for (int i = 0; i < 4; i++) {
                bA_n[i] = bptr[(size_t)i * KVL + (t + 1) * 32];
                bB_n[i] = bptr[(size_t)i * KVL + (t + 1) * 32 + 16];
            }
        }

        /* issue K(t+1)+V(t+1) into the other buffers, then drain group t */
        if (t + 1 < NT) {
            int tn = t + 1;
            uint32_t kdst = skb + (uint32_t)(tn & 1) * (K_ELEMS * 4);
            uint32_t vdst = svb + (uint32_t)(tn & 1) * (V_ELEMS * 4);
#pragma unroll
            for (int k = 0; k < 4; k++) {
                int jr = jr_[k];
                int jg = kb0 + tn * 32 + jr;
                const float *srck, *srcv;
                if (jg < KVL - QL) {
                    size_t off = ((size_t)b * KVL + jg + QL) * HD + c4v;
                    srck = cache_k + off; srcv = cache_v + off;
                } else {
                    size_t mrow = (size_t)(b * QL + (jg - (KVL - QL))) * NQKV;
                    srck = g_qkv + mrow + 2048 + c4v;
                    srcv = g_qkv + mrow + 2176 + c4v;
                }
                cp16(kdst + (uint32_t)((jr * KSTR + c4v) * 4), srck);
                cp16(vdst + (uint32_t)((jr * VSTR + c4v) * 4), srcv);
            }
            CP_COMMIT();
            CP_WAIT1();
        } else {
            CP_WAIT0();
        }
        __syncthreads();                 /* K(t),V(t) visible to all */

        const float* sKb = sK + (t & 1) * K_ELEMS;
        const float* sVb = sV + (t & 1) * V_ELEMS;

        /* ---- S = Q K^T (f32x2 over e), kept in registers ---- */
        u64 accA[4], accB[4];
#pragma unroll
        for (int i = 0; i < 4; i++) { accA[i] = 0ull; accB[i] = 0ull; }
        {
            const float* kp0 = &sKb[stx * KSTR];
            const float* kp1 = &sKb[(stx + 16) * KSTR];
#pragma unroll 4
            for (int e = 0; e < 128; e += 4) {
                ulonglong2 kA = *(const ulonglong2*)&kp0[e];
                ulonglong2 kB = *(const ulonglong2*)&kp1[e];
#pragma unroll
                for (int i = 0; i < 4; i++) {
                    ulonglong2 qv = *(const ulonglong2*)&sQ[(r0 + i) * QSTR + e];
                    fma2(accA[i], qv.x, kA.x); fma2(accA[i], qv.y, kA.y);
                    fma2(accB[i], qv.x, kB.x); fma2(accB[i], qv.y, kB.y);
                }
            }
        }

        /* ---- online softmax: half-warp shfl reductions ---- */
#pragma unroll
        for (int i = 0; i < 4; i++) {
            float2 a = unpk(accA[i]);
            float2 c = unpk(accB[i]);
            float vA = (a.x + a.y) * SCALE + bA[i];
            float vB = (c.x + c.y) * SCALE + bB[i];
            float mx = fmaxf(vA, vB);
            mx = fmaxf(mx, __shfl_xor_sync(0xffffffffu, mx, 8, 16));
            mx = fmaxf(mx, __shfl_xor_sync(0xffffffffu, mx, 4, 16));
            mx = fmaxf(mx, __shfl_xor_sync(0xffffffffu, mx, 2, 16));
            mx = fmaxf(mx, __shfl_xor_sync(0xffffffffu, mx, 1, 16));
            float mn = fmaxf(mreg[i], mx);
            float al = __expf(mreg[i] - mn);
            float pa = __expf(vA - mn);
            float pb = __expf(vB - mn);
            float ls = pa + pb;
            ls += __shfl_xor_sync(0xffffffffu, ls, 8, 16);
            ls += __shfl_xor_sync(0xffffffffu, ls, 4, 16);
            ls += __shfl_xor_sync(0xffffffffu, ls, 2, 16);
            ls += __shfl_xor_sync(0xffffffffu, ls, 1, 16);
            lreg[i] = lreg[i] * al + ls;
            mreg[i] = mn;
            /* stage P as floats (warp-private rows) */
            sPf[(r0 + i) * PSTR + stx]      = pa;
            sPf[(r0 + i) * PSTR + stx + 16] = pb;
            u64 a2 = pack2(al);
            mul2(oacc[i][0], a2); mul2(oacc[i][1], a2);
            mul2(oacc[i][2], a2); mul2(oacc[i][3], a2);
        }
        __syncwarp();

        /* ---- O += P V : broadcast P floats, conflict-free V LDS.64 ---- */
        {
            const int c0 = 2 * stx;      /* cols c0+32*cidx, +1 */
#pragma unroll 4
            for (int j2 = 0; j2 < 16; j2++) {
                const float* vp0 = &sVb[(2 * j2) * VSTR + c0];
                const float* vp1 = &sVb[(2 * j2 + 1) * VSTR + c0];
                u64 v00 = *(const u64*)&vp0[0];
                u64 v01 = *(const u64*)&vp0[32];
                u64 v02 = *(const u64*)&vp0[64];
                u64 v03 = *(const u64*)&vp0[96];
                u64 v10 = *(const u64*)&vp1[0];
                u64 v11 = *(const u64*)&vp1[32];
                u64 v12 = *(const u64*)&vp1[64];
                u64 v13 = *(const u64*)&vp1[96];
#pragma unroll
                for (int i = 0; i < 4; i++) {
                    float2 pf = *(const float2*)&sPf[(r0 + i) * PSTR + 2 * j2];
                    u64 px = pack2(pf.x);
                    u64 py = pack2(pf.y);
                    fma2(oacc[i][0], px, v00);
                    fma2(oacc[i][1], px, v01);
                    fma2(oacc[i][2], px, v02);
                    fma2(oacc[i][3], px, v03);
                    fma2(oacc[i][0], py, v10);
                    fma2(oacc[i][1], py, v11);
                    fma2(oacc[i][2], py, v12);
                    fma2(oacc[i][3], py, v13);
                }
            }
        }
    }

    /* ---- epilogue: partial O (cols 2*stx+32*cidx) and (m,l) ---- */
#pragma unroll
    for (int i = 0; i < 4; i++) {
        int r = r0 + i;
        size_t base = (((size_t)b * 64 + r) * NSPLIT + s) * HD + 2 * stx;
#pragma unroll
        for (int c = 0; c < 4; c++) {
            float2 f = unpk(oacc[i][c]);
            *(float2*)&g_po[base + 32 * c] = f;
        }
    }
    if (stx == 0) {
#pragma unroll
        for (int i = 0; i < 4; i++) {
            size_t pb = (((size_t)b * 64 + r0 + i) * NSPLIT + s) * 2;
            g_pml[pb]     = mreg[i];
            g_pml[pb + 1] = lreg[i];
        }
    }
}

/* ------------------------------------------------------------------ */
/* Combine the NSPLIT partial softmax results                          */
/* ------------------------------------------------------------------ */
__global__ void combine_kernel()
{
    int b = blockIdx.x, tid = threadIdx.x;
    int r = tid >> 2, e0 = (tid & 3) * 32;
    size_t pbase = ((size_t)b * 64 + r) * NSPLIT;

    float ms[NSPLIT], ls[NSPLIT], w[NSPLIT];
    float M = -1e30f;
#pragma unroll
    for (int s = 0; s < NSPLIT; s++) {
        ms[s] = g_pml[(pbase + s) * 2];
        ls[s] = g_pml[(pbase + s) * 2 + 1];
        M = fmaxf(M, ms[s]);
    }
    float L = 0.f;
#pragma unroll
    for (int s = 0; s < NSPLIT; s++) { w[s] = __expf(ms[s] - M); L += ls[s] * w[s]; }
    float inv = 1.f / L;
#pragma unroll
    for (int s = 0; s < NSPLIT; s++) w[s] *= inv;

    int q = r & 3, h = r >> 2;
    float* dst = g_o + (size_t)(b * QL + q) * DIM + h * HD;
    for (int e = e0; e < e0 + 32; e += 4) {
        float4 acc = make_float4(0.f, 0.f, 0.f, 0.f);
#pragma unroll
        for (int s = 0; s < NSPLIT; s++) {
            float4 v = *(const float4*)&g_po[(pbase + s) * HD + e];
            acc.x += v.x * w[s]; acc.y += v.y * w[s];
            acc.z += v.z * w[s]; acc.w += v.w * w[s];
        }
        *(float4*)&dst[e] = acc;
    }
}

/* ------------------------------------------------------------------ */
/* Reduce split-K partials for output projection + bo -> d_out         */
/* ------------------------------------------------------------------ */
__global__ void reduce_out(const float* __restrict__ bo, float* __restrict__ out)
{
    int idx = blockIdx.x * 256 + threadIdx.x;
    int m = idx >> 9;
    int n = (idx & 511) << 2;
    float4 s = *(const float4*)&bo[n];
#pragma unroll
    for (int sk = 0; sk < NSPLIT; sk++) {
        float4 v = *(const float4*)&g_part[(size_t)(sk * M_ + m) * NQKV + n];
        s.x += v.x; s.y += v.y; s.z += v.z; s.w += v.w;
    }
    *(float4*)&out[(size_t)m * DIM + n] = s;
}

/* ------------------------------------------------------------------ */
extern "C" void kernel_launch(void* const* d_in, const int* in_sizes, int n_in,
                              void* d_out, int out_size)
{
    const float* x         = (const float*)d_in[0];
    const float* attn_bias = (const float*)d_in[1];
    const float* cache_k   = (const float*)d_in[2];
    const float* cache_v   = (const float*)d_in[3];
    const float* wq        = (const float*)d_in[4];
    const float* bq        = (const float*)d_in[5];
    const float* wk        = (const float*)d_in[6];
    const float* bk        = (const float*)d_in[7];
    const float* wv        = (const float*)d_in[8];
    const float* bv        = (const float*)d_in[9];
    const float* wo        = (const float*)d_in[10];
    const float* bo        = (const float*)d_in[11];
    float*       out       = (float*)d_out;

    cudaFuncSetAttribute(attn_kernel,
                         cudaFuncAttributeMaxDynamicSharedMemorySize, ATTN_SMEM);

    float* go_ptr = nullptr;
    cudaGetSymbolAddress((void**)&go_ptr, g_o);

    /* 1) QKV projections (split-K) */
    gemm64<<<dim3(32, 2, NSPLIT), 256>>>(x, DIM, wq, 2048, 0);
    gemm64<<<dim3(2, 2, NSPLIT), 256>>>(x, DIM, wk, 128, 2048);
    gemm64<<<dim3(2, 2, NSPLIT), 256>>>(x, DIM, wv, 128, 2176);
    reduce_qkv<<<288, 256>>>(bq, bk, bv);

    /* 2) fused flash attention, split over KV */
    attn_kernel<<<dim3(NSPLIT, B_), 256, ATTN_SMEM>>>(attn_bias, cache_k, cache_v);

    /* 3) combine split-softmax partials */
    combine_kernel<<<B_, 256>>>();

    /* 4) output projection (split-K) */
    gemm64<<<dim3(32, 2, NSPLIT), 256>>>(go_ptr, DIM, wo, DIM, 0);
    reduce_out<<<256, 256>>>(bo, out);
}

// round 11
// speedup vs baseline: 1.5953x; 1.2972x over previous
#include <cuda_runtime.h>
#include <cuda_bf16.h>
#include <cstdint>

typedef unsigned long long u64;

#define B_      32
#define QL      4
#define DIM     2048
#define HEADS   16
#define HD      128
#define KVL     8192
#define M_      (B_*QL)
#define NQKV    2304
#define NSPLIT  8
#define CHUNK   (KVL/NSPLIT)     /* 1024 keys per CTA      */
#define NT3     (CHUNK/64)       /* 16 tiles of 64 keys    */
#define SCALE   0.08838834764831845f
#define SMAX    16.0f

/* ------------------------------------------------------------------ */
__device__ float g_part[NSPLIT * M_ * NQKV];
__device__ float g_qkv [M_ * NQKV];
__device__ float g_po  [(size_t)B_ * 64 * NSPLIT * HD];
__device__ float g_pml [B_ * 64 * NSPLIT * 2];
__device__ float g_o   [M_ * DIM];

/* ---------------- packed f32x2 (projection GEMMs) ------------------ */
__device__ __forceinline__ u64 pack2(float x) {
    u64 r; asm("mov.b64 %0, {%1, %1};" : "=l"(r) : "f"(x)); return r;
}
__device__ __forceinline__ void fma2(u64& d, u64 a, u64 b) {
    asm("fma.rn.f32x2 %0, %1, %2, %0;" : "+l"(d) : "l"(a), "l"(b));
}
__device__ __forceinline__ float2 unpk(u64 v) {
    float2 f; asm("mov.b64 {%0, %1}, %2;" : "=f"(f.x), "=f"(f.y) : "l"(v)); return f;
}

/* ---------------- mma.sync helpers (sm_80+ path) ------------------- */
__device__ __forceinline__ void ldsm_x4(uint32_t* a, uint32_t addr) {
    asm volatile("ldmatrix.sync.aligned.m8n8.x4.shared.b16 {%0,%1,%2,%3}, [%4];"
        : "=r"(a[0]), "=r"(a[1]), "=r"(a[2]), "=r"(a[3]) : "r"(addr));
}
__device__ __forceinline__ void ldsm_x4t(uint32_t* a, uint32_t addr) {
    asm volatile("ldmatrix.sync.aligned.m8n8.x4.trans.shared.b16 {%0,%1,%2,%3}, [%4];"
        : "=r"(a[0]), "=r"(a[1]), "=r"(a[2]), "=r"(a[3]) : "r"(addr));
}
__device__ __forceinline__ void mma_bf16(float* c, const uint32_t* a,
                                         uint32_t b0, uint32_t b1) {
    asm volatile("mma.sync.aligned.m16n8k16.row.col.f32.bf16.bf16.f32 "
        "{%0,%1,%2,%3}, {%4,%5,%6,%7}, {%8,%9}, {%0,%1,%2,%3};"
        : "+f"(c[0]), "+f"(c[1]), "+f"(c[2]), "+f"(c[3])
        : "r"(a[0]), "r"(a[1]), "r"(a[2]), "r"(a[3]), "r"(b0), "r"(b1));
}

__device__ __forceinline__ uint32_t bfpair(float a, float b) {
    __nv_bfloat162 t = __floats2bfloat162_rn(a, b);
    return *(uint32_t*)&t;
}
/* hi bf16 pair + lo residual bf16 pair */
__device__ __forceinline__ uint32_t hipair(float a, float b, uint32_t& lo) {
    __nv_bfloat16 ha = __float2bfloat16(a), hb = __float2bfloat16(b);
    lo = bfpair(a - __bfloat162float(ha), b - __bfloat162float(hb));
    __nv_bfloat162 h; h.x = ha; h.y = hb;
    return *(uint32_t*)&h;
}

/* ------------------------------------------------------------------ */
/* Projection GEMM (unchanged scalar split-K)                          */
/* ------------------------------------------------------------------ */
__global__ __launch_bounds__(256) void gemm64(
    const float* __restrict__ A, int lda,
    const float* __restrict__ B, int ldb,
    int ncol0)
{
    __shared__ u64   sA2[16][65];
    __shared__ float sB[16][64];

    const int tid = threadIdx.x;
    const int tx  = tid & 15, ty = tid >> 4;
    const int m0  = blockIdx.y * 64, n0 = blockIdx.x * 64;
    const int k0  = blockIdx.z * 256;

    u64 acc[4][2];
#pragma unroll
    for (int i = 0; i < 4; i++) { acc[i][0] = 0ull; acc[i][1] = 0ull; }

    const int ar = tid >> 2, akq = tid & 3;
    const int bk = tid >> 4, bc  = tid & 15;

    for (int kt = 0; kt < 256; kt += 16) {
        float4 av = *(const float4*)&A[(size_t)(m0 + ar) * lda + k0 + kt + akq * 4];
        float4 bv = *(const float4*)&B[(size_t)(k0 + kt + bk) * ldb + n0 + bc * 4];
        __syncthreads();
        sA2[akq * 4 + 0][ar] = pack2(av.x);
        sA2[akq * 4 + 1][ar] = pack2(av.y);
        sA2[akq * 4 + 2][ar] = pack2(av.z);
        sA2[akq * 4 + 3][ar] = pack2(av.w);
        *(float4*)&sB[bk][bc * 4] = bv;
        __syncthreads();
#pragma unroll
        for (int kk = 0; kk < 16; kk++) {
            ulonglong2 b2 = *(const ulonglong2*)&sB[kk][tx * 4];
#pragma unroll
            for (int i = 0; i < 4; i++) {
                u64 a2 = sA2[kk][ty * 4 + i];
                fma2(acc[i][0], a2, b2.x);
                fma2(acc[i][1], a2, b2.y);
            }
        }
    }

    float* dst = g_part + (size_t)(blockIdx.z * M_ + m0) * NQKV + ncol0 + n0;
#pragma unroll
    for (int i = 0; i < 4; i++) {
        float2 f0 = unpk(acc[i][0]), f1 = unpk(acc[i][1]);
        *(float4*)&dst[(size_t)(ty * 4 + i) * NQKV + tx * 4] =
            make_float4(f0.x, f0.y, f1.x, f1.y);
    }
}

__global__ void reduce_qkv(const float* __restrict__ bq,
                           const float* __restrict__ bk,
                           const float* __restrict__ bv)
{
    int idx = blockIdx.x * 256 + threadIdx.x;
    if (idx >= M_ * NQKV / 4) return;
    int m = idx / (NQKV / 4);
    int n = (idx % (NQKV / 4)) * 4;
    float4 s = make_float4(0.f, 0.f, 0.f, 0.f);
#pragma unroll
    for (int sk = 0; sk < NSPLIT; sk++) {
        float4 v = *(const float4*)&g_part[(size_t)(sk * M_ + m) * NQKV + n];
        s.x += v.x; s.y += v.y; s.z += v.z; s.w += v.w;
    }
    float4 bb;
    if (n < 2048)       bb = *(const float4*)&bq[n];
    else if (n < 2176)  bb = *(const float4*)&bk[n - 2048];
    else                bb = *(const float4*)&bv[n - 2176];
    s.x += bb.x; s.y += bb.y; s.z += bb.z; s.w += bb.w;
    *(float4*)&g_qkv[(size_t)m * NQKV + n] = s;
}

/* ------------------------------------------------------------------ */
/* mma.sync flash attention (bf16 hi/lo split, fixed-shift softmax)    */
/*  grid (NSPLIT, B), 128 threads (4 warps, each 16 rows)              */
/*  smem 96KB: Qh|Ql (64x128 bf16) Kh|Kl Vh|Vl (64 keys x 128)         */
/*  swizzle: byte ^ ((row&7)<<4), 256B rows                            */
/* ------------------------------------------------------------------ */
#define OQH3 0
#define OQL3 16384
#define OKH3 32768
#define OKL3 49152
#define OVH3 65536
#define OVL3 81920
#define SMEM3 98304

__global__ __launch_bounds__(128, 2) void attn3(
    const float* __restrict__ bias,
    const float* __restrict__ cache_k,
    const float* __restrict__ cache_v)
{
    extern __shared__ char smem[];
    const uint32_t sb = (uint32_t)__cvta_generic_to_shared(smem);
    const int tid  = threadIdx.x;
    const int lane = tid & 31, wid = tid >> 5;
    const int s    = blockIdx.x, b = blockIdx.y;
    const int g    = lane >> 2, tig = lane & 3;
    const int wr0  = wid * 16;

    const int jr = tid >> 1;             /* row handled by this thread (0..63) */
    const int e0 = (tid & 1) * 64;       /* fp32-column half                   */
    const uint32_t rb = (uint32_t)(jr * 256);
    const uint32_t sx = ((uint32_t)jr & 7u) << 4;

    /* ---- Q -> smem (bf16 hi/lo, SCALE folded) ---- */
    {
        const float* qp = &g_qkv[(size_t)(b * QL + (jr & 3)) * NQKV + (jr >> 2) * HD + e0];
#pragma unroll
        for (int i = 0; i < 16; i++) {
            float4 q4 = *(const float4*)&qp[4 * i];
            q4.x *= SCALE; q4.y *= SCALE; q4.z *= SCALE; q4.w *= SCALE;
            uint32_t off = rb + (((uint32_t)(2 * (e0 + 4 * i))) ^ sx);
            uint32_t l01, l23;
            uint32_t h01 = hipair(q4.x, q4.y, l01);
            uint32_t h23 = hipair(q4.z, q4.w, l23);
            *(uint32_t*)(smem + OQH3 + off)     = h01;
            *(uint32_t*)(smem + OQH3 + off + 4) = h23;
            *(uint32_t*)(smem + OQL3 + off)     = l01;
            *(uint32_t*)(smem + OQL3 + off + 4) = l23;
        }
    }

    float oacc[16][4];
#pragma unroll
    for (int n = 0; n < 16; n++)
#pragma unroll
        for (int c = 0; c < 4; c++) oacc[n][c] = 0.f;
    float lacc0 = 0.f, lacc1 = 0.f;

    const size_t brow0 = ((size_t)b * 64 + wr0 + g) * KVL;

    for (int t = 0; t < NT3; t++) {
        const int kb = s * CHUNK + t * 64;

        /* ---- K,V tile -> smem (bf16 hi/lo), rolling-cache patched ---- */
        {
            int jg = kb + jr;
            const float *srck, *srcv;
            if (jg < KVL - QL) {
                size_t off = ((size_t)b * KVL + jg + QL) * HD + e0;
                srck = cache_k + off; srcv = cache_v + off;
            } else {
                size_t mrow = (size_t)(b * QL + (jg - (KVL - QL))) * NQKV;
                srck = g_qkv + mrow + 2048 + e0;
                srcv = g_qkv + mrow + 2176 + e0;
            }
#pragma unroll
            for (int i = 0; i < 16; i++) {
                float4 k4 = *(const float4*)&srck[4 * i];
                uint32_t off = rb + (((uint32_t)(2 * (e0 + 4 * i))) ^ sx);
                uint32_t l01, l23;
                uint32_t h01 = hipair(k4.x, k4.y, l01);
                uint32_t h23 = hipair(k4.z, k4.w, l23);
                *(uint32_t*)(smem + OKH3 + off)     = h01;
                *(uint32_t*)(smem + OKH3 + off + 4) = h23;
                *(uint32_t*)(smem + OKL3 + off)     = l01;
                *(uint32_t*)(smem + OKL3 + off + 4) = l23;
            }
#pragma unroll
            for (int i = 0; i < 16; i++) {
                float4 v4 = *(const float4*)&srcv[4 * i];
                uint32_t off = rb + (((uint32_t)(2 * (e0 + 4 * i))) ^ sx);
                uint32_t l01, l23;
                uint32_t h01 = hipair(v4.x, v4.y, l01);
                uint32_t h23 = hipair(v4.z, v4.w, l23);
                *(uint32_t*)(smem + OVH3 + off)     = h01;
                *(uint32_t*)(smem + OVH3 + off + 4) = h23;
                *(uint32_t*)(smem + OVL3 + off)     = l01;
                *(uint32_t*)(smem + OVL3 + off + 4) = l23;
            }
        }
        __syncthreads();

        /* ---- bias for this tile (consumed after S-mma) ---- */
        float2 bA[8], bB[8];
#pragma unroll
        for (int n = 0; n < 8; n++) {
            bA[n] = *(const float2*)&bias[brow0 + kb + n * 8 + 2 * tig];
            bB[n] = *(const float2*)&bias[brow0 + 8 * KVL + kb + n * 8 + 2 * tig];
        }

        /* ---- S = Q K^T : hh + hl + lh passes, fp32 accum ---- */
        float sacc[8][4];
#pragma unroll
        for (int n = 0; n < 8; n++)
#pragma unroll
            for (int c = 0; c < 4; c++) sacc[n][c] = 0.f;

#pragma unroll
        for (int e = 0; e < 8; e++) {
            const uint32_t cb = (uint32_t)(e * 32);
            /* A frags (Q): rows wr0..+15 */
            const int arow = wr0 + (lane & 15);
            uint32_t aoff = (uint32_t)(arow * 256)
                + ((cb + (uint32_t)((lane >> 4) << 4)) ^ (((uint32_t)arow & 7u) << 4));
            uint32_t aqh[4], aql[4];
            ldsm_x4(aqh, sb + OQH3 + aoff);
            ldsm_x4(aql, sb + OQL3 + aoff);
#pragma unroll
            for (int np = 0; np < 4; np++) {
                const int krow = np * 16 + ((lane >> 4) & 1) * 8 + (lane & 7);
                uint32_t koff = (uint32_t)(krow * 256)
                    + (((uint32_t)(cb + ((lane >> 3) & 1) * 16)) ^ (((uint32_t)krow & 7u) << 4));
                uint32_t bh[4], bl[4];
                ldsm_x4(bh, sb + OKH3 + koff);
                ldsm_x4(bl, sb + OKL3 + koff);
                mma_bf16(sacc[2*np],   aqh, bh[0], bh[1]);
                mma_bf16(sacc[2*np+1], aqh, bh[2], bh[3]);
                mma_bf16(sacc[2*np],   aql, bh[0], bh[1]);
                mma_bf16(sacc[2*np+1], aql, bh[2], bh[3]);
                mma_bf16(sacc[2*np],   aqh, bl[0], bl[1]);
                mma_bf16(sacc[2*np+1], aqh, bl[2], bl[3]);
            }
        }

        /* ---- softmax (fixed shift) + O += P V, per k16 group ---- */
#pragma unroll
        for (int kk = 0; kk < 4; kk++) {
            uint32_t pah[4], pal[4];
            /* S tiles 2kk, 2kk+1 -> A fragment of P (the FA2 identity) */
#pragma unroll
            for (int h = 0; h < 2; h++) {
                const int n = 2 * kk + h;
                float p0 = __expf(sacc[n][0] + bA[n].x - SMAX);
                float p1 = __expf(sacc[n][1] + bA[n].y - SMAX);
                float p2 = __expf(sacc[n][2] + bB[n].x - SMAX);
                float p3 = __expf(sacc[n][3] + bB[n].y - SMAX);
                lacc0 += p0 + p1;
                lacc1 += p2 + p3;
                pah[2*h]   = hipair(p0, p1, pal[2*h]);
                pah[2*h+1] = hipair(p2, p3, pal[2*h+1]);
            }
#pragma unroll
            for (int np = 0; np < 8; np++) {
                const int vrow = kk * 16 + ((lane >> 3) & 1) * 8 + (lane & 7);
                uint32_t voff = (uint32_t)(vrow * 256)
                    + (((uint32_t)(np * 32 + ((lane >> 4) & 1) * 16)) ^ (((uint32_t)vrow & 7u) << 4));
                uint32_t vh[4], vl[4];
                ldsm_x4t(vh, sb + OVH3 + voff);
                ldsm_x4t(vl, sb + OVL3 + voff);
                mma_bf16(oacc[2*np],   pah, vh[0], vh[1]);
                mma_bf16(oacc[2*np+1], pah, vh[2], vh[3]);
                mma_bf16(oacc[2*np],   pal, vh[0], vh[1]);
                mma_bf16(oacc[2*np+1], pal, vh[2], vh[3]);
                mma_bf16(oacc[2*np],   pah, vl[0], vl[1]);
                mma_bf16(oacc[2*np+1], pah, vl[2], vl[3]);
            }
        }
        __syncthreads();   /* done reading K/V before next tile's stores */
    }

    /* ---- epilogue: unnormalized partial O + row sums l ---- */
    {
        const int row0 = b * 64 + wr0 + g;
#pragma unroll
        for (int n = 0; n < 16; n++) {
            int col = n * 8 + 2 * tig;
            *(float2*)&g_po[((size_t)row0 * NSPLIT + s) * HD + col] =
                make_float2(oacc[n][0], oacc[n][1]);
            *(float2*)&g_po[((size_t)(row0 + 8) * NSPLIT + s) * HD + col] =
                make_float2(oacc[n][2], oacc[n][3]);
        }
        lacc0 += __shfl_xor_sync(0xffffffffu, lacc0, 1);
        lacc0 += __shfl_xor_sync(0xffffffffu, lacc0, 2);
        lacc1 += __shfl_xor_sync(0xffffffffu, lacc1, 1);
        lacc1 += __shfl_xor_sync(0xffffffffu, lacc1, 2);
        if (tig == 0) {
            g_pml[row0 * NSPLIT + s]       = lacc0;
            g_pml[(row0 + 8) * NSPLIT + s] = lacc1;
        }
    }
}

/* ------------------------------------------------------------------ */
/* Combine: plain sum over splits, divide by total l                   */
/* ------------------------------------------------------------------ */
__global__ void combine2()
{
    int b = blockIdx.x, tid = threadIdx.x;   /* 128 threads */
    int r = tid >> 1, half = tid & 1;
    float lt = 0.f;
#pragma unroll
    for (int s = 0; s < NSPLIT; s++) lt += g_pml[(b * 64 + r) * NSPLIT + s];
    float inv = 1.f / lt;
    int q = r & 3, h = r >> 2;
    float* dst = g_o + (size_t)(b * QL + q) * DIM + h * HD + half * 64;
    size_t pb = ((size_t)(b * 64 + r) * NSPLIT) * HD + half * 64;
    for (int e = 0; e < 64; e += 4) {
        float4 acc = make_float4(0.f, 0.f, 0.f, 0.f);
#pragma unroll
        for (int s = 0; s < NSPLIT; s++) {
            float4 v = *(const float4*)&g_po[pb + (size_t)s * HD + e];
            acc.x += v.x; acc.y += v.y; acc.z += v.z; acc.w += v.w;
        }
        acc.x *= inv; acc.y *= inv; acc.z *= inv; acc.w *= inv;
        *(float4*)&dst[e] = acc;
    }
}

/* ------------------------------------------------------------------ */
__global__ void reduce_out(const float* __restrict__ bo, float* __restrict__ out)
{
    int idx = blockIdx.x * 256 + threadIdx.x;
    int m = idx >> 9;
    int n = (idx & 511) << 2;
    float4 s = *(const float4*)&bo[n];
#pragma unroll
    for (int sk = 0; sk < NSPLIT; sk++) {
        float4 v = *(const float4*)&g_part[(size_t)(sk * M_ + m) * NQKV + n];
        s.x += v.x; s.y += v.y; s.z += v.z; s.w += v.w;
    }
    *(float4*)&out[(size_t)m * DIM + n] = s;
}

/* ------------------------------------------------------------------ */
extern "C" void kernel_launch(void* const* d_in, const int* in_sizes, int n_in,
                              void* d_out, int out_size)
{
    const float* x         = (const float*)d_in[0];
    const float* attn_bias = (const float*)d_in[1];
    const float* cache_k   = (const float*)d_in[2];
    const float* cache_v   = (const float*)d_in[3];
    const float* wq        = (const float*)d_in[4];
    const float* bq        = (const float*)d_in[5];
    const float* wk        = (const float*)d_in[6];
    const float* bk        = (const float*)d_in[7];
    const float* wv        = (const float*)d_in[8];
    const float* bv        = (const float*)d_in[9];
    const float* wo        = (const float*)d_in[10];
    const float* bo        = (const float*)d_in[11];
    float*       out       = (float*)d_out;

    cudaFuncSetAttribute(attn3,
                         cudaFuncAttributeMaxDynamicSharedMemorySize, SMEM3);

    float* go_ptr = nullptr;
    cudaGetSymbolAddress((void**)&go_ptr, g_o);

    /* 1) QKV projections */
    gemm64<<<dim3(32, 2, NSPLIT), 256>>>(x, DIM, wq, 2048, 0);
    gemm64<<<dim3(2, 2, NSPLIT), 256>>>(x, DIM, wk, 128, 2048);
    gemm64<<<dim3(2, 2, NSPLIT), 256>>>(x, DIM, wv, 128, 2176);
    reduce_qkv<<<288, 256>>>(bq, bk, bv);

    /* 2) tensor-core flash attention */
    attn3<<<dim3(NSPLIT, B_), 128, SMEM3>>>(attn_bias, cache_k, cache_v);

    /* 3) combine splits */
    combine2<<<B_, 128>>>();

    /* 4) output projection */
    gemm64<<<dim3(32, 2, NSPLIT), 256>>>(go_ptr, DIM, wo, DIM, 0);
    reduce_out<<<256, 256>>>(bo, out);
}